// round 14
// baseline (speedup 1.0000x reference)
#include <cuda_runtime.h>
#include <cuda_bf16.h>
#include <stdint.h>

#define BATCH 16384
#define KS 20
#define DIM 256
#define NH 4
#define EPSF 1e-8f

typedef __nv_bfloat16 bf16;

// ---------------- scratch (device globals; allocations are forbidden) ------
__device__ bf16 g_xh [(long)BATCH * 256], g_xl [(long)BATCH * 256];
__device__ bf16 g_mh [(long)BATCH * 256], g_ml [(long)BATCH * 256];  // hmean
__device__ bf16 g_qh [(long)BATCH * 256], g_ql [(long)BATCH * 256];
__device__ bf16 g_sh [(long)BATCH * 1024], g_sl [(long)BATCH * 1024];
__device__ bf16 g_ch [(long)BATCH * 256], g_cl [(long)BATCH * 256];
#define W_TOTAL 425984
__device__ bf16 g_wh[W_TOTAL], g_wl[W_TOTAL];
__device__ float g_had [(long)BATCH * 128];
__device__ float g_himp[(long)BATCH * 256];
__device__ float g_qk  [(long)BATCH * 1024];
__device__ float g_N   [(long)BATCH * 1024];
__device__ float g_Z   [(long)BATCH * NH];
__device__ float g_dot0[(long)BATCH * NH];
__device__ float g_stat[BATCH];

__device__ __forceinline__ float warp_sum(float v) {
    #pragma unroll
    for (int o = 16; o; o >>= 1) v += __shfl_down_sync(0xffffffffu, v, o);
    return v;
}
__device__ __forceinline__ void store_split(bf16* ph, bf16* pl, float v) {
    bf16 h = __float2bfloat16(v);
    *ph = h;
    *pl = __float2bfloat16(v - __bfloat162float(h));
}

// ---------------- conv: weights (layout below) + x, one launch -------------
//   [0,65536)        wq      [256][256]
//   [65536,98304)    ad_w1   [128][256]
//   [98304,229376)   imp_w1  [256][512]
//   [229376,294912)  wkT     [4][256 n][64 i]   (transposed)
//   [294912,360448)  wv      [256][256]
//   [360448,425984)  w_out   [256][256]
#define CONV_TOTAL (W_TOTAL + BATCH * 256)
__global__ __launch_bounds__(256) void conv_all(
    const float* __restrict__ ad_w1, const float* __restrict__ imp_w1,
    const float* __restrict__ w_in,  const float* __restrict__ w_out,
    const float* __restrict__ x)
{
    long i = (long)blockIdx.x * 256 + threadIdx.x;
    if (i >= CONV_TOTAL) return;
    if (i >= W_TOTAL) {
        long idx = i - W_TOTAL;
        store_split(g_xh + idx, g_xl + idx, x[idx]);
        return;
    }
    int ii = (int)i;
    float v;
    if (ii < 65536)       v = w_in[ii];
    else if (ii < 98304)  v = ad_w1[ii - 65536];
    else if (ii < 229376) v = imp_w1[ii - 98304];
    else if (ii < 294912) {
        int j = ii - 229376;
        int z = j >> 14, r = (j >> 6) & 255, c = j & 63;
        v = w_in[65536 + (z * 64 + c) * 256 + r];
    }
    else if (ii < 360448) v = w_in[131072 + (ii - 294912)];
    else                  v = w_out[ii - 360448];
    bf16 h = __float2bfloat16(v);
    g_wh[ii] = h;
    g_wl[ii] = __float2bfloat16(v - __bfloat162float(h));
}

// ---------------- K1: stats + st rows 1..19 + attention partials -----------
// sm holds DECAYED rows from the start; stats use raw register copies.
__global__ __launch_bounds__(256, 4) void k1_stats(
    const float* __restrict__ storage, const float* __restrict__ xmsg,
    float* __restrict__ out_st)
{
    __shared__ float sm[KS][DIM];      // sm[j] = storage[j] * 0.95^j
    __shared__ float qks[NH * DIM];
    __shared__ float xs[DIM];
    __shared__ float smask[KS];
    __shared__ float sred[8];
    __shared__ float sc[NH][KS];
    __shared__ float spart[2][NH][20];
    __shared__ float smp[8][KS];       // mask partials per warp

    int b = blockIdx.x, tid = threadIdx.x;
    int w = tid >> 5, lane = tid & 31;
    const float* row = storage + (long)b * KS * DIM;
    float vals[KS];                    // RAW values
    {
        float dec = 1.f;
        #pragma unroll
        for (int j = 0; j < KS; j++) {
            vals[j] = row[j * DIM + tid];
            sm[j][tid] = vals[j] * dec;
            dec *= 0.95f;
        }
    }
    xs[tid] = xmsg[(long)b * DIM + tid];
    #pragma unroll
    for (int h = 0; h < NH; h++)
        qks[h * DIM + tid] = g_qk[(long)b * 1024 + h * DIM + tid];

    // mask partials via registers + shuffles (no smem reads of rows)
    float keep = 0.f;
    #pragma unroll
    for (int j = 0; j < KS; j++) {
        float s = warp_sum(fabsf(vals[j]));
        s = __shfl_sync(0xffffffffu, s, 0);
        if (lane == j) keep = s;
    }
    if (lane < KS) smp[w][lane] = keep;
    __syncthreads();

    if (tid < KS) {
        float t = 0.f;
        #pragma unroll
        for (int i = 0; i < 8; i++) t += smp[i][tid];
        smask[tid] = (t > 0.f) ? 1.f : 0.f;
    }
    __syncthreads();

    float denom = EPSF;
    #pragma unroll
    for (int j = 0; j < KS; j++) denom += smask[j];

    int d = tid;
    float m = 0.f;
    #pragma unroll
    for (int j = 0; j < KS; j++) m += vals[j] * smask[j];
    float hmean = m / denom;
    float v = 0.f;
    #pragma unroll
    for (int j = 0; j < KS; j++) {
        float df = vals[j] - hmean;
        v += df * df * smask[j];
    }
    float hstd = sqrtf(v / denom);

    float xd = xs[d];
    float z = fabsf((xd - hmean) / (hstd + EPSF));
    float c = (z > 2.0f) ? 1.f : 0.f;
    c = warp_sum(c);
    if (lane == 0) sred[w] = c;
    __syncthreads();
    if (tid == 0) {
        float t = 0.f;
        #pragma unroll
        for (int i = 0; i < 8; i++) t += sred[i];
        g_stat[b] = t / (float)DIM;
    }

    store_split(g_mh + (long)b * 256 + d, g_ml + (long)b * 256 + d, hmean);

    // st rows 1..19 straight from registers (decay folded)
    {
        float* orow = out_st + (long)b * KS * DIM;
        float dec = 1.f;
        #pragma unroll
        for (int jj = 0; jj < KS - 1; jj++) {
            orow[(jj + 1) * DIM + d] = vals[jj] * dec;
            dec *= 0.95f;
        }
    }

    // scores: warp w owns (h = w&3, d-half = w>>2); qk slice cached in regs
    {
        int h = w & 3, half = w >> 2;
        int fi = half * 32 + lane;
        const float4* qh4 = (const float4*)(qks + h * DIM);
        float4 qa = qh4[fi];
        #pragma unroll
        for (int jj = 0; jj < KS - 1; jj++) {
            float4 sv = ((const float4*)sm[jj])[fi];
            float s = qa.x * sv.x + qa.y * sv.y + qa.z * sv.z + qa.w * sv.w;
            s = warp_sum(s);
            if (lane == 0) spart[half][h][jj] = s;
        }
        {
            float4 xv = ((const float4*)xs)[fi];
            float s = qa.x * xv.x + qa.y * xv.y + qa.z * xv.z + qa.w * xv.w;
            s = warp_sum(s);
            if (lane == 0) spart[half][h][19] = s;
        }
    }
    __syncthreads();
    if (tid < 80) {
        int hh = tid / 20, t = tid % 20;
        float s = (spart[0][hh][t] + spart[1][hh][t]) * 0.125f;
        if (t < 19) sc[hh][t] = expf(s);
        else g_dot0[(long)b * NH + hh] = s;
    }
    __syncthreads();

    if (tid < NH) {
        float zz = 0.f;
        #pragma unroll
        for (int jj = 0; jj < KS - 1; jj++) zz += sc[tid][jj];
        g_Z[(long)b * NH + tid] = zz;
    }

    // N[h][d] = sum_jj e[h][jj] * decayed[jj][d]
    float acc[NH] = {0.f, 0.f, 0.f, 0.f};
    {
        float dec = 1.f;
        #pragma unroll
        for (int jj = 0; jj < KS - 1; jj++) {
            float sv = vals[jj] * dec;
            #pragma unroll
            for (int h = 0; h < NH; h++) acc[h] += sc[h][jj] * sv;
            dec *= 0.95f;
        }
    }
    #pragma unroll
    for (int h = 0; h < NH; h++)
        g_N[(long)b * 1024 + h * DIM + d] = acc[h];
}

// ---------------- kf: anomaly + importance + st row0 + final attention -----
__global__ __launch_bounds__(256) void kf(
    const float* __restrict__ ad_w2, const float* __restrict__ ad_b2,
    const float* __restrict__ imp_w2, const float* __restrict__ imp_b2,
    const float* __restrict__ xmsg, float* __restrict__ out_st)
{
    __shared__ float sred1[8], sred2[8], se0[NH], sfac[NH];
    __shared__ float simp;
    int b = blockIdx.x, tid = threadIdx.x;
    int w = tid >> 5, lane = tid & 31;

    float p1 = (tid < 128) ? g_had[(long)b * 128 + tid] * ad_w2[tid] : 0.f;
    float p2 = g_himp[(long)b * 256 + tid] * imp_w2[tid];
    p1 = warp_sum(p1);
    p2 = warp_sum(p2);
    if (lane == 0) { sred1[w] = p1; sred2[w] = p2; }
    __syncthreads();
    if (tid == 0) {
        float d1 = ad_b2[0], d2 = imp_b2[0];
        #pragma unroll
        for (int i = 0; i < 8; i++) { d1 += sred1[i]; d2 += sred2[i]; }
        float learned = 1.f / (1.f + expf(-d1));
        float anom = 0.5f * g_stat[b] + 0.5f * learned;
        float sp = fmaxf(d2, 0.f) + log1pf(expf(-fabsf(d2)));
        simp = sp * (1.f + anom);
    }
    __syncthreads();
    float imp = simp;
    if (tid < NH) {
        float e0 = expf(imp * g_dot0[(long)b * NH + tid]);
        se0[tid] = e0;
        sfac[tid] = 1.f / (g_Z[(long)b * NH + tid] + e0);
    }
    float x = xmsg[(long)b * 256 + tid];
    float st0 = x * imp;
    out_st[(long)b * KS * DIM + tid] = st0;
    __syncthreads();

    #pragma unroll
    for (int h = 0; h < NH; h++) {
        float s = (g_N[(long)b * 1024 + h * 256 + tid] + se0[h] * st0) * sfac[h];
        long o = (long)b * 1024 + h * 256 + tid;
        store_split(g_sh + o, g_sl + o, s);
    }
}

// ---------------- pipelined bf16x3 TC GEMM, 128x64 tile --------------------
#define PITCH 80
#define SZ_A 10240
#define SZ_B 5120
#define OFF_AL (SZ_A)
#define OFF_BH (2 * SZ_A)
#define OFF_BL (2 * SZ_A + SZ_B)
#define STAGE  (2 * SZ_A + 2 * SZ_B)   // 30720
#define SMEM_DYN (2 * STAGE)           // 61440 (NST=2)

#define CP16(dst, src) asm volatile( \
    "cp.async.cg.shared.global [%0], [%1], 16;" :: "r"(dst), "l"(src))
#define CP_COMMIT() asm volatile("cp.async.commit_group;" ::: "memory")
#define CP_WAIT1()  asm volatile("cp.async.wait_group 1;" ::: "memory")
#define CP_WAIT0()  asm volatile("cp.async.wait_group 0;" ::: "memory")

__device__ __forceinline__ void ldmx4(uint32_t* r, uint32_t addr) {
    asm volatile("ldmatrix.sync.aligned.m8n8.x4.shared.b16 {%0,%1,%2,%3},[%4];"
                 : "=r"(r[0]), "=r"(r[1]), "=r"(r[2]), "=r"(r[3]) : "r"(addr));
}
__device__ __forceinline__ void mma16816(float* c, const uint32_t* a,
                                         const uint32_t* b) {
    asm volatile(
        "mma.sync.aligned.m16n8k16.row.col.f32.bf16.bf16.f32 "
        "{%0,%1,%2,%3},{%4,%5,%6,%7},{%8,%9},{%0,%1,%2,%3};"
        : "+f"(c[0]), "+f"(c[1]), "+f"(c[2]), "+f"(c[3])
        : "r"(a[0]), "r"(a[1]), "r"(a[2]), "r"(a[3]), "r"(b[0]), "r"(b[1]));
}
__device__ __forceinline__ uint32_t smem_u32(const void* p) {
    return (uint32_t)__cvta_generic_to_shared(p);
}

// MERGED=1: q+ad fused (n0<256 -> bf16 q pairs; n0>=256 -> relu fp32 g_had)
template<int ASEL, int KTOT, int SPLITK, int CBF, int ACT, int MERGED>
__global__ __launch_bounds__(256, 3) void gemm_pl(
    int lda, int aZ, int wOff, int ldb, int bZ,
    const float* __restrict__ bias, const float* __restrict__ bias2,
    int biasZ, float* __restrict__ Cext, int cSel, int ldc, int cZ)
{
    extern __shared__ __align__(128) char dsm[];
    uint32_t sm0 = smem_u32(dsm);
    const int NST = 2;

    const bf16 *Ah, *Al;
    if (ASEL == 1 || ASEL == 2) { Ah = g_xh; Al = g_xl; }
    else if (ASEL == 3) { Ah = g_qh; Al = g_ql; }
    else if (ASEL == 4) { Ah = g_sh; Al = g_sl; }
    else                { Ah = g_ch; Al = g_cl; }
    float* Cf = Cext;
    if (cSel == 2) Cf = g_had;
    else if (cSel == 3) Cf = g_himp;
    else if (cSel == 5) Cf = g_qk;

    int z  = blockIdx.z;
    int m0 = blockIdx.x * 128;
    int n0 = blockIdx.y * 64;
    long aOff = (long)aZ * z;
    long bOff = (long)wOff + (long)bZ * z;

    int tid = threadIdx.x;
    int warp = tid >> 5, lane = tid & 31;
    int wm = (warp >> 1) * 32, wn = (warp & 1) * 32;
    int lr = lane >> 2, lc = lane & 3;

    int arow = tid >> 1, acs = (tid & 1) * 2;
    int brow = tid >> 2, bcs = tid & 3;
    uint32_t aDst = arow * PITCH + acs * 16;
    uint32_t bDst = brow * PITCH + bcs * 16;
    long aRowOff = (long)(m0 + arow) * lda + aOff + acs * 8;
    long bSrc = bOff + (long)(n0 + brow) * ldb + bcs * 8;

    uint32_t aFrag = (uint32_t)((wm + (lane & 15)) * PITCH + (lane >> 4) * 16);
    uint32_t bFrag = (uint32_t)((wn + ((lane >> 4) << 3) + (lane & 7)) * PITCH
                                + ((lane >> 3) & 1) * 16);

    const int NCH = KTOT / 32;

    auto issue = [&](int ch, int st) {
        uint32_t sb = sm0 + st * STAGE;
        int c0 = ch * 32;
        const bf16* ah_ = Ah;
        const bf16* al_ = Al;
        int kk = c0;
        if (SPLITK < KTOT && c0 >= SPLITK) { ah_ = g_mh; al_ = g_ml; kk = c0 - SPLITK; }
        long ga = aRowOff + kk;
        CP16(sb + aDst,                ah_ + ga);
        CP16(sb + aDst + 16,           ah_ + ga + 8);
        CP16(sb + OFF_AL + aDst,       al_ + ga);
        CP16(sb + OFF_AL + aDst + 16,  al_ + ga + 8);
        long gb = bSrc + c0;
        CP16(sb + OFF_BH + bDst, g_wh + gb);
        CP16(sb + OFF_BL + bDst, g_wl + gb);
    };

    float acc[2][4][4];
    #pragma unroll
    for (int i = 0; i < 2; i++)
        #pragma unroll
        for (int j = 0; j < 4; j++)
            #pragma unroll
            for (int q = 0; q < 4; q++) acc[i][j][q] = 0.f;

    issue(0, 0);
    CP_COMMIT();

    #pragma unroll
    for (int ch = 0; ch < NCH; ch++) {
        if (ch + NST - 1 < NCH) {
            issue(ch + NST - 1, (ch + NST - 1) % NST);
            CP_COMMIT();
        }
        int pend = ((ch + NST < NCH) ? (ch + NST) : NCH) - ch - 1;
        if (pend >= 1) CP_WAIT1(); else CP_WAIT0();
        __syncthreads();

        uint32_t sb = sm0 + (ch % NST) * STAGE;
        #pragma unroll
        for (int ks = 0; ks < 2; ks++) {
            uint32_t kb = ks * 32;
            uint32_t ah[2][4], al[2][4], bh[2][4], bl[2][4];
            #pragma unroll
            for (int am = 0; am < 2; am++) {
                ldmx4(ah[am], sb + aFrag + am * (16 * PITCH) + kb);
                ldmx4(al[am], sb + OFF_AL + aFrag + am * (16 * PITCH) + kb);
            }
            #pragma unroll
            for (int anp = 0; anp < 2; anp++) {
                ldmx4(bh[anp], sb + OFF_BH + bFrag + anp * (16 * PITCH) + kb);
                ldmx4(bl[anp], sb + OFF_BL + bFrag + anp * (16 * PITCH) + kb);
            }
            #pragma unroll
            for (int am = 0; am < 2; am++)
                #pragma unroll
                for (int an = 0; an < 4; an++) {
                    const uint32_t* bph = &bh[an >> 1][(an & 1) * 2];
                    const uint32_t* bpl = &bl[an >> 1][(an & 1) * 2];
                    mma16816(acc[am][an], ah[am], bph);
                    mma16816(acc[am][an], ah[am], bpl);
                    mma16816(acc[am][an], al[am], bph);
                }
        }
        __syncthreads();
    }

    // ---- epilogue ----
    bool adPath = MERGED && (n0 >= 256);
    #pragma unroll
    for (int am = 0; am < 2; am++) {
        #pragma unroll
        for (int an = 0; an < 4; an++) {
            int row0 = m0 + wm + am * 16 + lr;
            int col  = n0 + wn + an * 8 + lc * 2;
            float v0 = acc[am][an][0], v1 = acc[am][an][1];
            float v2 = acc[am][an][2], v3 = acc[am][an][3];
            if (adPath) {
                int cc = col - 256;
                float b0 = bias2[cc], b1 = bias2[cc + 1];
                v0 = fmaxf(v0 + b0, 0.f); v1 = fmaxf(v1 + b1, 0.f);
                v2 = fmaxf(v2 + b0, 0.f); v3 = fmaxf(v3 + b1, 0.f);
                *(float2*)(g_had + (long)row0 * 128 + cc) = make_float2(v0, v1);
                *(float2*)(g_had + (long)(row0 + 8) * 128 + cc) = make_float2(v2, v3);
            } else {
                float b0 = 0.f, b1 = 0.f;
                if (bias) {
                    b0 = bias[biasZ * z + col];
                    b1 = bias[biasZ * z + col + 1];
                }
                v0 += b0; v1 += b1; v2 += b0; v3 += b1;
                if (ACT == 1) {
                    v0 = fmaxf(v0, 0.f); v1 = fmaxf(v1, 0.f);
                    v2 = fmaxf(v2, 0.f); v3 = fmaxf(v3, 0.f);
                }
                long off = (long)cZ * z + col;
                if (CBF) {
                    bf16* Ch = (CBF == 1) ? g_qh : g_ch;
                    bf16* Cl = (CBF == 1) ? g_ql : g_cl;
                    long p0 = (long)row0 * ldc + off;
                    long p1 = (long)(row0 + 8) * ldc + off;
                    store_split(Ch + p0, Cl + p0, v0);
                    store_split(Ch + p0 + 1, Cl + p0 + 1, v1);
                    store_split(Ch + p1, Cl + p1, v2);
                    store_split(Ch + p1 + 1, Cl + p1 + 1, v3);
                } else {
                    *(float2*)(Cf + (long)row0 * ldc + off) = make_float2(v0, v1);
                    *(float2*)(Cf + (long)(row0 + 8) * ldc + off) = make_float2(v2, v3);
                }
            }
        }
    }
}

#define NOSPLIT (1 << 30)

// ---------------------------------------------------------------------------
extern "C" void kernel_launch(void* const* d_in, const int* in_sizes, int n_in,
                              void* d_out, int out_size) {
    const float* storage = (const float*)d_in[0];
    const float* x       = (const float*)d_in[1];
    const float* ad_w1   = (const float*)d_in[2];
    const float* ad_b1   = (const float*)d_in[3];
    const float* ad_w2   = (const float*)d_in[4];
    const float* ad_b2   = (const float*)d_in[5];
    const float* imp_w1  = (const float*)d_in[6];
    const float* imp_b1  = (const float*)d_in[7];
    const float* imp_w2  = (const float*)d_in[8];
    const float* imp_b2  = (const float*)d_in[9];
    const float* w_in    = (const float*)d_in[10];
    const float* b_in    = (const float*)d_in[11];
    const float* w_out   = (const float*)d_in[12];
    const float* b_out   = (const float*)d_in[13];

    float* st  = (float*)d_out;                       // [B,K,D]
    float* agg = st + (long)BATCH * KS * DIM;         // [B,D]

    cudaFuncSetAttribute(gemm_pl<1, 256, NOSPLIT, 1, 0, 1>,
                         cudaFuncAttributeMaxDynamicSharedMemorySize, SMEM_DYN);
    cudaFuncSetAttribute(gemm_pl<3, 64, NOSPLIT, 0, 0, 0>,
                         cudaFuncAttributeMaxDynamicSharedMemorySize, SMEM_DYN);
    cudaFuncSetAttribute(gemm_pl<2, 512, 256, 0, 1, 0>,
                         cudaFuncAttributeMaxDynamicSharedMemorySize, SMEM_DYN);
    cudaFuncSetAttribute(gemm_pl<4, 256, NOSPLIT, 2, 0, 0>,
                         cudaFuncAttributeMaxDynamicSharedMemorySize, SMEM_DYN);
    cudaFuncSetAttribute(gemm_pl<5, 256, NOSPLIT, 0, 0, 0>,
                         cudaFuncAttributeMaxDynamicSharedMemorySize, SMEM_DYN);

    conv_all<<<(CONV_TOTAL + 255) / 256, 256>>>(ad_w1, imp_w1, w_in, w_out, x);
    // MERGED q+ad: cols 0..255 -> q (bf16 pairs, bias b_in); 256..383 -> ad hidden
    gemm_pl<1, 256, NOSPLIT, 1, 0, 1><<<dim3(128, 6, 1), 256, SMEM_DYN>>>(
        256, 0, 0, 256, 0, b_in, ad_b1, 0, nullptr, 0, 256, 0);
    // qk[b, z*256+n] = wkT[z][n][:] . q[b, z*64:] -> g_qk fp32
    gemm_pl<3, 64, NOSPLIT, 0, 0, 0><<<dim3(128, 4, 4), 256, SMEM_DYN>>>(
        256, 64, 229376, 64, 16384, nullptr, nullptr, 0, nullptr, 5, 1024, 256);
    // stats + st rows 1..19 + attention partials (N1, Z1, dot0)
    k1_stats<<<BATCH, 256>>>(storage, x, st);
    // imp-MLP hidden: relu([x|hmean] @ imp_w1^T + imp_b1) -> g_himp [B,256]
    gemm_pl<2, 512, 256, 0, 1, 0><<<dim3(128, 4, 1), 256, SMEM_DYN>>>(
        256, 0, 98304, 512, 0, imp_b1, nullptr, 0, nullptr, 3, 256, 0);
    // anomaly + importance + st row0 + final weighted sums -> g_sh/g_sl
    kf<<<BATCH, 256>>>(ad_w2, ad_b2, imp_w2, imp_b2, x, st);
    // ctx[b, z*64+n] = wv_z[n,:] . s[b,z,:] + bv -> g_ch/g_cl [B,256]
    gemm_pl<4, 256, NOSPLIT, 2, 0, 0><<<dim3(128, 1, 4), 256, SMEM_DYN>>>(
        1024, 256, 294912, 256, 16384, b_in + 512, nullptr, 64, nullptr, 0, 256, 64);
    // agg = ctx @ attn_out_w^T + attn_out_b -> d_out tail (fp32)
    gemm_pl<5, 256, NOSPLIT, 0, 0, 0><<<dim3(128, 4, 1), 256, SMEM_DYN>>>(
        256, 0, 360448, 256, 0, b_out, nullptr, 0, agg, 0, 256, 0);
    (void)in_sizes; (void)n_in; (void)out_size;
}

// round 15
// speedup vs baseline: 1.1265x; 1.1265x over previous
#include <cuda_runtime.h>
#include <cuda_bf16.h>
#include <stdint.h>

#define BATCH 16384
#define KS 20
#define DIM 256
#define NH 4
#define EPSF 1e-8f

typedef __nv_bfloat16 bf16;

// ---------------- scratch (device globals; allocations are forbidden) ------
__device__ bf16 g_xh [(long)BATCH * 256], g_xl [(long)BATCH * 256];
__device__ bf16 g_mh [(long)BATCH * 256], g_ml [(long)BATCH * 256];  // hmean
__device__ bf16 g_sh [(long)BATCH * 1024], g_sl [(long)BATCH * 1024];
__device__ bf16 g_ch [(long)BATCH * 256], g_cl [(long)BATCH * 256];
#define W_TOTAL 425984
__device__ bf16 g_wh[W_TOTAL], g_wl[W_TOTAL];
__device__ float g_had [(long)BATCH * 128];
__device__ float g_himp[(long)BATCH * 256];
__device__ float g_qk  [(long)BATCH * 1024];
__device__ float g_N   [(long)BATCH * 1024];
__device__ float g_Z   [(long)BATCH * NH];
__device__ float g_dot0[(long)BATCH * NH];
__device__ float g_stat[BATCH];

__device__ __forceinline__ float warp_sum(float v) {
    #pragma unroll
    for (int o = 16; o; o >>= 1) v += __shfl_down_sync(0xffffffffu, v, o);
    return v;
}
__device__ __forceinline__ void store_split(bf16* ph, bf16* pl, float v) {
    bf16 h = __float2bfloat16(v);
    *ph = h;
    *pl = __float2bfloat16(v - __bfloat162float(h));
}

// ---------------- conv: weights + x, one launch ----------------------------
//   [0,65536)        wq      [256][256]
//   [65536,98304)    ad_w1   [128][256]
//   [98304,229376)   imp_w1  [256][512]
//   [229376,294912)  wkT     [4][256 n][64 i]   (transposed)
//   [294912,360448)  wv      [256][256]
//   [360448,425984)  w_out   [256][256]
#define CONV_TOTAL (W_TOTAL + BATCH * 256)
__global__ __launch_bounds__(256) void conv_all(
    const float* __restrict__ ad_w1, const float* __restrict__ imp_w1,
    const float* __restrict__ w_in,  const float* __restrict__ w_out,
    const float* __restrict__ x)
{
    long i = (long)blockIdx.x * 256 + threadIdx.x;
    if (i >= CONV_TOTAL) return;
    if (i >= W_TOTAL) {
        long idx = i - W_TOTAL;
        store_split(g_xh + idx, g_xl + idx, x[idx]);
        return;
    }
    int ii = (int)i;
    float v;
    if (ii < 65536)       v = w_in[ii];
    else if (ii < 98304)  v = ad_w1[ii - 65536];
    else if (ii < 229376) v = imp_w1[ii - 98304];
    else if (ii < 294912) {
        int j = ii - 229376;
        int z = j >> 14, r = (j >> 6) & 255, c = j & 63;
        v = w_in[65536 + (z * 64 + c) * 256 + r];
    }
    else if (ii < 360448) v = w_in[131072 + (ii - 294912)];
    else                  v = w_out[ii - 360448];
    bf16 h = __float2bfloat16(v);
    g_wh[ii] = h;
    g_wl[ii] = __float2bfloat16(v - __bfloat162float(h));
}

// ---------------- K1 (R10-exact): stats + st rows + attention partials -----
__global__ __launch_bounds__(256) void k1_stats(
    const float* __restrict__ storage, const float* __restrict__ xmsg,
    float* __restrict__ out_st)
{
    __shared__ float sm[KS][DIM];
    __shared__ float qks[NH * DIM];
    __shared__ float xs[DIM];
    __shared__ float smask[KS];
    __shared__ float sred[8];
    __shared__ float sc[NH][KS];

    int b = blockIdx.x, tid = threadIdx.x;
    const float* row = storage + (long)b * KS * DIM;
    float vals[KS];
    #pragma unroll
    for (int j = 0; j < KS; j++) {
        vals[j] = row[j * DIM + tid];
        sm[j][tid] = vals[j];
    }
    xs[tid] = xmsg[(long)b * DIM + tid];
    #pragma unroll
    for (int h = 0; h < NH; h++)
        qks[h * DIM + tid] = g_qk[(long)b * 1024 + h * DIM + tid];
    __syncthreads();

    int w = tid >> 5, lane = tid & 31;
    for (int j = w; j < KS; j += 8) {
        const float4* sj = (const float4*)sm[j];
        float4 a = sj[lane], c = sj[lane + 32];
        float s = fabsf(a.x) + fabsf(a.y) + fabsf(a.z) + fabsf(a.w)
                + fabsf(c.x) + fabsf(c.y) + fabsf(c.z) + fabsf(c.w);
        s = warp_sum(s);
        if (lane == 0) smask[j] = (s > 0.f) ? 1.f : 0.f;
    }
    __syncthreads();

    float denom = EPSF;
    #pragma unroll
    for (int j = 0; j < KS; j++) denom += smask[j];

    int d = tid;
    float m = 0.f;
    #pragma unroll
    for (int j = 0; j < KS; j++) m += vals[j] * smask[j];
    float hmean = m / denom;
    float v = 0.f;
    #pragma unroll
    for (int j = 0; j < KS; j++) {
        float df = vals[j] - hmean;
        v += df * df * smask[j];
    }
    float hstd = sqrtf(v / denom);

    float xd = xs[d];
    float z = fabsf((xd - hmean) / (hstd + EPSF));
    float c = (z > 2.0f) ? 1.f : 0.f;
    c = warp_sum(c);
    if (lane == 0) sred[w] = c;
    __syncthreads();
    if (tid == 0) {
        float t = 0.f;
        #pragma unroll
        for (int i = 0; i < 8; i++) t += sred[i];
        g_stat[b] = t / (float)DIM;
    }

    store_split(g_mh + (long)b * 256 + d, g_ml + (long)b * 256 + d, hmean);

    float dec = 1.f;
    float* orow = out_st + (long)b * KS * DIM;
    #pragma unroll
    for (int jj = 0; jj < KS - 1; jj++) {
        float sv = vals[jj] * dec;
        vals[jj] = sv;
        sm[jj][d] = sv;
        orow[(jj + 1) * DIM + d] = sv;
        dec *= 0.95f;
    }
    __syncthreads();

    #pragma unroll
    for (int u = 0; u < 10; u++) {
        int id = w + u * 8;
        if (id < 76) {
            int h = id / 19, jj = id % 19;
            const float4* qh = (const float4*)(qks + h * DIM);
            const float4* sj = (const float4*)sm[jj];
            float4 a0 = qh[lane],      b0 = sj[lane];
            float4 a1 = qh[lane + 32], b1 = sj[lane + 32];
            float s = a0.x * b0.x + a0.y * b0.y + a0.z * b0.z + a0.w * b0.w
                    + a1.x * b1.x + a1.y * b1.y + a1.z * b1.z + a1.w * b1.w;
            s = warp_sum(s);
            if (lane == 0) sc[h][jj] = expf(s * 0.125f);
        } else {
            int h = id - 76;
            const float4* qh = (const float4*)(qks + h * DIM);
            const float4* xv = (const float4*)xs;
            float4 a0 = qh[lane],      b0 = xv[lane];
            float4 a1 = qh[lane + 32], b1 = xv[lane + 32];
            float s = a0.x * b0.x + a0.y * b0.y + a0.z * b0.z + a0.w * b0.w
                    + a1.x * b1.x + a1.y * b1.y + a1.z * b1.z + a1.w * b1.w;
            s = warp_sum(s);
            if (lane == 0) g_dot0[(long)b * NH + h] = s * 0.125f;
        }
    }
    __syncthreads();

    if (tid < NH) {
        float zz = 0.f;
        #pragma unroll
        for (int jj = 0; jj < KS - 1; jj++) zz += sc[tid][jj];
        g_Z[(long)b * NH + tid] = zz;
    }

    float acc[NH] = {0.f, 0.f, 0.f, 0.f};
    #pragma unroll
    for (int jj = 0; jj < KS - 1; jj++) {
        float sv = vals[jj];
        #pragma unroll
        for (int h = 0; h < NH; h++) acc[h] += sc[h][jj] * sv;
    }
    #pragma unroll
    for (int h = 0; h < NH; h++)
        g_N[(long)b * 1024 + h * DIM + d] = acc[h];
}

// ---------------- kf: anomaly + importance + st row0 + final attention -----
__global__ __launch_bounds__(256) void kf(
    const float* __restrict__ ad_w2, const float* __restrict__ ad_b2,
    const float* __restrict__ imp_w2, const float* __restrict__ imp_b2,
    const float* __restrict__ xmsg, float* __restrict__ out_st)
{
    __shared__ float sred1[8], sred2[8], se0[NH], sfac[NH];
    __shared__ float simp;
    int b = blockIdx.x, tid = threadIdx.x;
    int w = tid >> 5, lane = tid & 31;

    float p1 = (tid < 128) ? g_had[(long)b * 128 + tid] * ad_w2[tid] : 0.f;
    float p2 = g_himp[(long)b * 256 + tid] * imp_w2[tid];
    p1 = warp_sum(p1);
    p2 = warp_sum(p2);
    if (lane == 0) { sred1[w] = p1; sred2[w] = p2; }
    __syncthreads();
    if (tid == 0) {
        float d1 = ad_b2[0], d2 = imp_b2[0];
        #pragma unroll
        for (int i = 0; i < 8; i++) { d1 += sred1[i]; d2 += sred2[i]; }
        float learned = 1.f / (1.f + expf(-d1));
        float anom = 0.5f * g_stat[b] + 0.5f * learned;
        float sp = fmaxf(d2, 0.f) + log1pf(expf(-fabsf(d2)));
        simp = sp * (1.f + anom);
    }
    __syncthreads();
    float imp = simp;
    if (tid < NH) {
        float e0 = expf(imp * g_dot0[(long)b * NH + tid]);
        se0[tid] = e0;
        sfac[tid] = 1.f / (g_Z[(long)b * NH + tid] + e0);
    }
    float x = xmsg[(long)b * 256 + tid];
    float st0 = x * imp;
    out_st[(long)b * KS * DIM + tid] = st0;
    __syncthreads();

    #pragma unroll
    for (int h = 0; h < NH; h++) {
        float s = (g_N[(long)b * 1024 + h * 256 + tid] + se0[h] * st0) * sfac[h];
        long o = (long)b * 1024 + h * 256 + tid;
        store_split(g_sh + o, g_sl + o, s);
    }
}

// ---------------- GEMM common pieces ---------------------------------------
#define PITCH 80
#define SZ_A 10240
#define SZ_B 5120
#define OFF_AL (SZ_A)
#define OFF_BH (2 * SZ_A)
#define OFF_BL (2 * SZ_A + SZ_B)
#define STAGE  (2 * SZ_A + 2 * SZ_B)   // 30720
#define SMEM_DYN (2 * STAGE)           // 61440

#define CP16(dst, src) asm volatile( \
    "cp.async.cg.shared.global [%0], [%1], 16;" :: "r"(dst), "l"(src))
#define CP_COMMIT() asm volatile("cp.async.commit_group;" ::: "memory")
#define CP_WAIT1()  asm volatile("cp.async.wait_group 1;" ::: "memory")
#define CP_WAIT0()  asm volatile("cp.async.wait_group 0;" ::: "memory")

__device__ __forceinline__ void ldmx4(uint32_t* r, uint32_t addr) {
    asm volatile("ldmatrix.sync.aligned.m8n8.x4.shared.b16 {%0,%1,%2,%3},[%4];"
                 : "=r"(r[0]), "=r"(r[1]), "=r"(r[2]), "=r"(r[3]) : "r"(addr));
}
__device__ __forceinline__ void mma16816(float* c, const uint32_t* a,
                                         const uint32_t* b) {
    asm volatile(
        "mma.sync.aligned.m16n8k16.row.col.f32.bf16.bf16.f32 "
        "{%0,%1,%2,%3},{%4,%5,%6,%7},{%8,%9},{%0,%1,%2,%3};"
        : "+f"(c[0]), "+f"(c[1]), "+f"(c[2]), "+f"(c[3])
        : "r"(a[0]), "r"(a[1]), "r"(a[2]), "r"(a[3]), "r"(b[0]), "r"(b[1]));
}
__device__ __forceinline__ uint32_t smem_u32(const void* p) {
    return (uint32_t)__cvta_generic_to_shared(p);
}

// ---------------- generic pipelined bf16x3 GEMM ----------------------------
template<int ASEL, int KTOT, int SPLITK, int CBF, int ACT>
__global__ __launch_bounds__(256, 3) void gemm_pl(
    int lda, int aZ, int wOff, int ldb, int bZ,
    const float* __restrict__ bias, int biasZ,
    float* __restrict__ Cext, int cSel, int ldc, int cZ)
{
    extern __shared__ __align__(128) char dsm[];
    uint32_t sm0 = smem_u32(dsm);
    const int NST = 2;

    const bf16 *Ah, *Al;
    if (ASEL == 1 || ASEL == 2) { Ah = g_xh; Al = g_xl; }
    else if (ASEL == 4) { Ah = g_sh; Al = g_sl; }
    else                { Ah = g_ch; Al = g_cl; }
    float* Cf = Cext;
    if (cSel == 3) Cf = g_himp;

    int z  = blockIdx.z;
    int m0 = blockIdx.x * 128;
    int n0 = blockIdx.y * 64;
    long aOff = (long)aZ * z;
    long bOff = (long)wOff + (long)bZ * z;

    int tid = threadIdx.x;
    int warp = tid >> 5, lane = tid & 31;
    int wm = (warp >> 1) * 32, wn = (warp & 1) * 32;
    int lr = lane >> 2, lc = lane & 3;

    int arow = tid >> 1, acs = (tid & 1) * 2;
    int brow = tid >> 2, bcs = tid & 3;
    uint32_t aDst = arow * PITCH + acs * 16;
    uint32_t bDst = brow * PITCH + bcs * 16;
    long aRowOff = (long)(m0 + arow) * lda + aOff + acs * 8;
    long bSrc = bOff + (long)(n0 + brow) * ldb + bcs * 8;

    uint32_t aFrag = (uint32_t)((wm + (lane & 15)) * PITCH + (lane >> 4) * 16);
    uint32_t bFrag = (uint32_t)((wn + ((lane >> 4) << 3) + (lane & 7)) * PITCH
                                + ((lane >> 3) & 1) * 16);

    const int NCH = KTOT / 32;

    auto issue = [&](int ch, int st) {
        uint32_t sb = sm0 + st * STAGE;
        int c0 = ch * 32;
        const bf16* ah_ = Ah;
        const bf16* al_ = Al;
        int kk = c0;
        if (SPLITK < KTOT && c0 >= SPLITK) { ah_ = g_mh; al_ = g_ml; kk = c0 - SPLITK; }
        long ga = aRowOff + kk;
        CP16(sb + aDst,                ah_ + ga);
        CP16(sb + aDst + 16,           ah_ + ga + 8);
        CP16(sb + OFF_AL + aDst,       al_ + ga);
        CP16(sb + OFF_AL + aDst + 16,  al_ + ga + 8);
        long gb = bSrc + c0;
        CP16(sb + OFF_BH + bDst, g_wh + gb);
        CP16(sb + OFF_BL + bDst, g_wl + gb);
    };

    float acc[2][4][4];
    #pragma unroll
    for (int i = 0; i < 2; i++)
        #pragma unroll
        for (int j = 0; j < 4; j++)
            #pragma unroll
            for (int q = 0; q < 4; q++) acc[i][j][q] = 0.f;

    issue(0, 0);
    CP_COMMIT();

    #pragma unroll
    for (int ch = 0; ch < NCH; ch++) {
        if (ch + NST - 1 < NCH) {
            issue(ch + NST - 1, (ch + NST - 1) % NST);
            CP_COMMIT();
        }
        int pend = ((ch + NST < NCH) ? (ch + NST) : NCH) - ch - 1;
        if (pend >= 1) CP_WAIT1(); else CP_WAIT0();
        __syncthreads();

        uint32_t sb = sm0 + (ch % NST) * STAGE;
        #pragma unroll
        for (int ks = 0; ks < 2; ks++) {
            uint32_t kb = ks * 32;
            uint32_t ah[2][4], al[2][4], bh[2][4], bl[2][4];
            #pragma unroll
            for (int am = 0; am < 2; am++) {
                ldmx4(ah[am], sb + aFrag + am * (16 * PITCH) + kb);
                ldmx4(al[am], sb + OFF_AL + aFrag + am * (16 * PITCH) + kb);
            }
            #pragma unroll
            for (int anp = 0; anp < 2; anp++) {
                ldmx4(bh[anp], sb + OFF_BH + bFrag + anp * (16 * PITCH) + kb);
                ldmx4(bl[anp], sb + OFF_BL + bFrag + anp * (16 * PITCH) + kb);
            }
            #pragma unroll
            for (int am = 0; am < 2; am++)
                #pragma unroll
                for (int an = 0; an < 4; an++) {
                    const uint32_t* bph = &bh[an >> 1][(an & 1) * 2];
                    const uint32_t* bpl = &bl[an >> 1][(an & 1) * 2];
                    mma16816(acc[am][an], ah[am], bph);
                    mma16816(acc[am][an], ah[am], bpl);
                    mma16816(acc[am][an], al[am], bph);
                }
        }
        __syncthreads();
    }

    #pragma unroll
    for (int am = 0; am < 2; am++) {
        #pragma unroll
        for (int an = 0; an < 4; an++) {
            int row0 = m0 + wm + am * 16 + lr;
            int col  = n0 + wn + an * 8 + lc * 2;
            float b0 = 0.f, b1 = 0.f;
            if (bias) {
                b0 = bias[biasZ * z + col];
                b1 = bias[biasZ * z + col + 1];
            }
            float v0 = acc[am][an][0] + b0, v1 = acc[am][an][1] + b1;
            float v2 = acc[am][an][2] + b0, v3 = acc[am][an][3] + b1;
            if (ACT == 1) {
                v0 = fmaxf(v0, 0.f); v1 = fmaxf(v1, 0.f);
                v2 = fmaxf(v2, 0.f); v3 = fmaxf(v3, 0.f);
            }
            long off = (long)cZ * z + col;
            if (CBF) {
                bf16* Ch = g_ch;
                bf16* Cl = g_cl;
                long p0 = (long)row0 * ldc + off;
                long p1 = (long)(row0 + 8) * ldc + off;
                store_split(Ch + p0, Cl + p0, v0);
                store_split(Ch + p0 + 1, Cl + p0 + 1, v1);
                store_split(Ch + p1, Cl + p1, v2);
                store_split(Ch + p1 + 1, Cl + p1 + 1, v3);
            } else {
                *(float2*)(Cf + (long)row0 * ldc + off) = make_float2(v0, v1);
                *(float2*)(Cf + (long)(row0 + 8) * ldc + off) = make_float2(v2, v3);
            }
        }
    }
}

// ---------------- fused q + ad + qk kernel ---------------------------------
// grid (128, 6): ny<4 -> q head ny, then in-block qk stage; ny>=4 -> ad hidden.
#define QPITCH 144                      // bytes/row for 64-bf16 Q tile
#define OFF_QL 18432                    // 128*144
#define OFF_B2 36864                    // stage-B weight buffers (2 chunks)
__global__ __launch_bounds__(256, 2) void gemm_qfused(
    const float* __restrict__ bq, const float* __restrict__ adb)
{
    extern __shared__ __align__(128) char dsm[];
    uint32_t sm0 = smem_u32(dsm);

    int ny = blockIdx.y;
    int m0 = blockIdx.x * 128;
    int n0 = ny * 64;

    int tid = threadIdx.x;
    int warp = tid >> 5, lane = tid & 31;
    int wm = (warp >> 1) * 32, wn = (warp & 1) * 32;
    int lr = lane >> 2, lc = lane & 3;

    int arow = tid >> 1, acs = (tid & 1) * 2;
    int brow = tid >> 2, bcs = tid & 3;
    uint32_t aDst = arow * PITCH + acs * 16;
    uint32_t bDst = brow * PITCH + bcs * 16;
    long aRowOff = (long)(m0 + arow) * 256 + acs * 8;
    long bSrc = (long)(n0 + brow) * 256 + bcs * 8;   // wq/ad rows contiguous at 0

    uint32_t aFrag = (uint32_t)((wm + (lane & 15)) * PITCH + (lane >> 4) * 16);
    uint32_t bFrag = (uint32_t)((wn + ((lane >> 4) << 3) + (lane & 7)) * PITCH
                                + ((lane >> 3) & 1) * 16);

    auto issue = [&](int ch, int st) {
        uint32_t sb = sm0 + st * STAGE;
        int c0 = ch * 32;
        long ga = aRowOff + c0;
        CP16(sb + aDst,                g_xh + ga);
        CP16(sb + aDst + 16,           g_xh + ga + 8);
        CP16(sb + OFF_AL + aDst,       g_xl + ga);
        CP16(sb + OFF_AL + aDst + 16,  g_xl + ga + 8);
        long gb = bSrc + c0;
        CP16(sb + OFF_BH + bDst, g_wh + gb);
        CP16(sb + OFF_BL + bDst, g_wl + gb);
    };

    float acc[2][4][4];
    #pragma unroll
    for (int i = 0; i < 2; i++)
        #pragma unroll
        for (int j = 0; j < 4; j++)
            #pragma unroll
            for (int q = 0; q < 4; q++) acc[i][j][q] = 0.f;

    issue(0, 0);
    CP_COMMIT();
    #pragma unroll
    for (int ch = 0; ch < 8; ch++) {
        if (ch + 1 < 8) { issue(ch + 1, (ch + 1) & 1); CP_COMMIT(); }
        if (ch + 1 < 8) CP_WAIT1(); else CP_WAIT0();
        __syncthreads();
        uint32_t sb = sm0 + (ch & 1) * STAGE;
        #pragma unroll
        for (int ks = 0; ks < 2; ks++) {
            uint32_t kb = ks * 32;
            uint32_t ah[2][4], al[2][4], bh[2][4], bl[2][4];
            #pragma unroll
            for (int am = 0; am < 2; am++) {
                ldmx4(ah[am], sb + aFrag + am * (16 * PITCH) + kb);
                ldmx4(al[am], sb + OFF_AL + aFrag + am * (16 * PITCH) + kb);
            }
            #pragma unroll
            for (int anp = 0; anp < 2; anp++) {
                ldmx4(bh[anp], sb + OFF_BH + bFrag + anp * (16 * PITCH) + kb);
                ldmx4(bl[anp], sb + OFF_BL + bFrag + anp * (16 * PITCH) + kb);
            }
            #pragma unroll
            for (int am = 0; am < 2; am++)
                #pragma unroll
                for (int an = 0; an < 4; an++) {
                    const uint32_t* bph = &bh[an >> 1][(an & 1) * 2];
                    const uint32_t* bpl = &bl[an >> 1][(an & 1) * 2];
                    mma16816(acc[am][an], ah[am], bph);
                    mma16816(acc[am][an], ah[am], bpl);
                    mma16816(acc[am][an], al[am], bph);
                }
        }
        __syncthreads();
    }

    if (ny >= 4) {
        // ---- ad hidden: relu + store fp32 ----
        #pragma unroll
        for (int am = 0; am < 2; am++)
            #pragma unroll
            for (int an = 0; an < 4; an++) {
                int row0 = m0 + wm + am * 16 + lr;
                int cc = n0 + wn + an * 8 + lc * 2 - 256;
                float b0 = adb[cc], b1 = adb[cc + 1];
                float v0 = fmaxf(acc[am][an][0] + b0, 0.f);
                float v1 = fmaxf(acc[am][an][1] + b1, 0.f);
                float v2 = fmaxf(acc[am][an][2] + b0, 0.f);
                float v3 = fmaxf(acc[am][an][3] + b1, 0.f);
                *(float2*)(g_had + (long)row0 * 128 + cc) = make_float2(v0, v1);
                *(float2*)(g_had + (long)(row0 + 8) * 128 + cc) = make_float2(v2, v3);
            }
        return;
    }

    // ---- stage A: q tile (bias added) -> smem bf16 hi/lo -------------------
    #pragma unroll
    for (int am = 0; am < 2; am++)
        #pragma unroll
        for (int an = 0; an < 4; an++) {
            int r0 = wm + am * 16 + lr;
            int ic = wn + an * 8 + lc * 2;
            float b0 = bq[n0 + ic], b1 = bq[n0 + ic + 1];
            float v0 = acc[am][an][0] + b0, v1 = acc[am][an][1] + b1;
            float v2 = acc[am][an][2] + b0, v3 = acc[am][an][3] + b1;
            store_split((bf16*)(dsm + r0 * QPITCH + ic * 2),
                        (bf16*)(dsm + OFF_QL + r0 * QPITCH + ic * 2), v0);
            store_split((bf16*)(dsm + r0 * QPITCH + ic * 2 + 2),
                        (bf16*)(dsm + OFF_QL + r0 * QPITCH + ic * 2 + 2), v1);
            store_split((bf16*)(dsm + (r0 + 8) * QPITCH + ic * 2),
                        (bf16*)(dsm + OFF_QL + (r0 + 8) * QPITCH + ic * 2), v2);
            store_split((bf16*)(dsm + (r0 + 8) * QPITCH + ic * 2 + 2),
                        (bf16*)(dsm + OFF_QL + (r0 + 8) * QPITCH + ic * 2 + 2), v3);
        }
    __syncthreads();

    // ---- stage B: qk[m, z*256 + sub*64 + n] = Q . wkT[z] -------------------
    int zz = ny;
    uint32_t aQ = sm0 + (uint32_t)((wm + (lane & 15)) * QPITCH + (lane >> 4) * 16);
    auto issueB = [&](int sub, int c) {
        uint32_t base = sm0 + OFF_B2 + c * (2 * SZ_B);
        long src = 229376 + (long)zz * 16384 + (long)(sub * 64 + brow) * 64
                 + c * 32 + bcs * 8;
        CP16(base + bDst, g_wh + src);
        CP16(base + SZ_B + bDst, g_wl + src);
    };

    for (int sub = 0; sub < 4; sub++) {
        if (sub) __syncthreads();
        issueB(sub, 0); CP_COMMIT();
        issueB(sub, 1); CP_COMMIT();

        float a2[2][4][4];
        #pragma unroll
        for (int i = 0; i < 2; i++)
            #pragma unroll
            for (int j = 0; j < 4; j++)
                #pragma unroll
                for (int q = 0; q < 4; q++) a2[i][j][q] = 0.f;

        #pragma unroll
        for (int c = 0; c < 2; c++) {
            if (c == 0) CP_WAIT1(); else CP_WAIT0();
            __syncthreads();
            uint32_t bb = sm0 + OFF_B2 + c * (2 * SZ_B);
            #pragma unroll
            for (int ks = 0; ks < 2; ks++) {
                uint32_t kbq = c * 64 + ks * 32;  // bytes into Q row
                uint32_t kb = ks * 32;
                uint32_t ah[2][4], al[2][4], bh[2][4], bl[2][4];
                #pragma unroll
                for (int am = 0; am < 2; am++) {
                    ldmx4(ah[am], aQ + am * (16 * QPITCH) + kbq);
                    ldmx4(al[am], aQ + OFF_QL + am * (16 * QPITCH) + kbq);
                }
                #pragma unroll
                for (int anp = 0; anp < 2; anp++) {
                    ldmx4(bh[anp], bb + bFrag + anp * (16 * PITCH) + kb);
                    ldmx4(bl[anp], bb + SZ_B + bFrag + anp * (16 * PITCH) + kb);
                }
                #pragma unroll
                for (int am = 0; am < 2; am++)
                    #pragma unroll
                    for (int an = 0; an < 4; an++) {
                        const uint32_t* bph = &bh[an >> 1][(an & 1) * 2];
                        const uint32_t* bpl = &bl[an >> 1][(an & 1) * 2];
                        mma16816(a2[am][an], ah[am], bph);
                        mma16816(a2[am][an], ah[am], bpl);
                        mma16816(a2[am][an], al[am], bph);
                    }
            }
        }
        // write g_qk
        #pragma unroll
        for (int am = 0; am < 2; am++)
            #pragma unroll
            for (int an = 0; an < 4; an++) {
                int row0 = m0 + wm + am * 16 + lr;
                int col = zz * 256 + sub * 64 + wn + an * 8 + lc * 2;
                *(float2*)(g_qk + (long)row0 * 1024 + col) =
                    make_float2(a2[am][an][0], a2[am][an][1]);
                *(float2*)(g_qk + (long)(row0 + 8) * 1024 + col) =
                    make_float2(a2[am][an][2], a2[am][an][3]);
            }
    }
}

#define NOSPLIT (1 << 30)

// ---------------------------------------------------------------------------
extern "C" void kernel_launch(void* const* d_in, const int* in_sizes, int n_in,
                              void* d_out, int out_size) {
    const float* storage = (const float*)d_in[0];
    const float* x       = (const float*)d_in[1];
    const float* ad_w1   = (const float*)d_in[2];
    const float* ad_b1   = (const float*)d_in[3];
    const float* ad_w2   = (const float*)d_in[4];
    const float* ad_b2   = (const float*)d_in[5];
    const float* imp_w1  = (const float*)d_in[6];
    const float* imp_b1  = (const float*)d_in[7];
    const float* imp_w2  = (const float*)d_in[8];
    const float* imp_b2  = (const float*)d_in[9];
    const float* w_in    = (const float*)d_in[10];
    const float* b_in    = (const float*)d_in[11];
    const float* w_out   = (const float*)d_in[12];
    const float* b_out   = (const float*)d_in[13];

    float* st  = (float*)d_out;                       // [B,K,D]
    float* agg = st + (long)BATCH * KS * DIM;         // [B,D]

    cudaFuncSetAttribute(gemm_qfused,
                         cudaFuncAttributeMaxDynamicSharedMemorySize, SMEM_DYN);
    cudaFuncSetAttribute(gemm_pl<2, 512, 256, 0, 1>,
                         cudaFuncAttributeMaxDynamicSharedMemorySize, SMEM_DYN);
    cudaFuncSetAttribute(gemm_pl<4, 256, NOSPLIT, 2, 0>,
                         cudaFuncAttributeMaxDynamicSharedMemorySize, SMEM_DYN);
    cudaFuncSetAttribute(gemm_pl<5, 256, NOSPLIT, 0, 0>,
                         cudaFuncAttributeMaxDynamicSharedMemorySize, SMEM_DYN);

    conv_all<<<(CONV_TOTAL + 255) / 256, 256>>>(ad_w1, imp_w1, w_in, w_out, x);
    // fused q (heads 0..3, + in-block qk -> g_qk) and ad hidden (ny 4,5)
    gemm_qfused<<<dim3(128, 6, 1), 256, SMEM_DYN>>>(b_in, ad_b1);
    // stats + st rows 1..19 + attention partials (N1, Z1, dot0)
    k1_stats<<<BATCH, 256>>>(storage, x, st);
    // imp-MLP hidden: relu([x|hmean] @ imp_w1^T + imp_b1) -> g_himp [B,256]
    gemm_pl<2, 512, 256, 0, 1><<<dim3(128, 4, 1), 256, SMEM_DYN>>>(
        256, 0, 98304, 512, 0, imp_b1, 0, nullptr, 3, 256, 0);
    // anomaly + importance + st row0 + final weighted sums -> g_sh/g_sl
    kf<<<BATCH, 256>>>(ad_w2, ad_b2, imp_w2, imp_b2, x, st);
    // ctx[b, z*64+n] = wv_z[n,:] . s[b,z,:] + bv -> g_ch/g_cl [B,256]
    gemm_pl<4, 256, NOSPLIT, 2, 0><<<dim3(128, 1, 4), 256, SMEM_DYN>>>(
        1024, 256, 294912, 256, 16384, b_in + 512, 64, nullptr, 0, 256, 64);
    // agg = ctx @ attn_out_w^T + attn_out_b -> d_out tail (fp32)
    gemm_pl<5, 256, NOSPLIT, 0, 0><<<dim3(128, 4, 1), 256, SMEM_DYN>>>(
        256, 0, 360448, 256, 0, b_out, 0, agg, 0, 256, 0);
    (void)in_sizes; (void)n_in; (void)out_size;
}

// round 16
// speedup vs baseline: 1.1404x; 1.0124x over previous
#include <cuda_runtime.h>
#include <cuda_bf16.h>
#include <stdint.h>

#define BATCH 16384
#define KS 20
#define DIM 256
#define NH 4
#define EPSF 1e-8f

typedef __nv_bfloat16 bf16;

// ---------------- scratch (device globals; allocations are forbidden) ------
__device__ bf16 g_xh [(long)BATCH * 256], g_xl [(long)BATCH * 256];
__device__ bf16 g_mh [(long)BATCH * 256], g_ml [(long)BATCH * 256];  // hmean
__device__ bf16 g_sh [(long)BATCH * 1024], g_sl [(long)BATCH * 1024];
__device__ bf16 g_ch [(long)BATCH * 256], g_cl [(long)BATCH * 256];
#define W_TOTAL 425984
__device__ bf16 g_wh[W_TOTAL], g_wl[W_TOTAL];
__device__ float g_qk  [(long)BATCH * 1024];
__device__ float g_N   [(long)BATCH * 1024];
__device__ float g_Z   [(long)BATCH * NH];
__device__ float g_dot0[(long)BATCH * NH];
__device__ float g_stat[BATCH];
__device__ float g_pimp[4][BATCH];   // imp-MLP partial dots (per n-block)
__device__ float g_pad [2][BATCH];   // ad-MLP partial dots

__device__ __forceinline__ float warp_sum(float v) {
    #pragma unroll
    for (int o = 16; o; o >>= 1) v += __shfl_down_sync(0xffffffffu, v, o);
    return v;
}
__device__ __forceinline__ void store_split(bf16* ph, bf16* pl, float v) {
    bf16 h = __float2bfloat16(v);
    *ph = h;
    *pl = __float2bfloat16(v - __bfloat162float(h));
}

// ---------------- conv: weights + x, one launch ----------------------------
//   [0,65536)        wq      [256][256]
//   [65536,98304)    ad_w1   [128][256]
//   [98304,229376)   imp_w1  [256][512]
//   [229376,294912)  wkT     [4][256 n][64 i]   (transposed)
//   [294912,360448)  wv      [256][256]
//   [360448,425984)  w_out   [256][256]
#define CONV_TOTAL (W_TOTAL + BATCH * 256)
__global__ __launch_bounds__(256) void conv_all(
    const float* __restrict__ ad_w1, const float* __restrict__ imp_w1,
    const float* __restrict__ w_in,  const float* __restrict__ w_out,
    const float* __restrict__ x)
{
    long i = (long)blockIdx.x * 256 + threadIdx.x;
    if (i >= CONV_TOTAL) return;
    if (i >= W_TOTAL) {
        long idx = i - W_TOTAL;
        store_split(g_xh + idx, g_xl + idx, x[idx]);
        return;
    }
    int ii = (int)i;
    float v;
    if (ii < 65536)       v = w_in[ii];
    else if (ii < 98304)  v = ad_w1[ii - 65536];
    else if (ii < 229376) v = imp_w1[ii - 98304];
    else if (ii < 294912) {
        int j = ii - 229376;
        int z = j >> 14, r = (j >> 6) & 255, c = j & 63;
        v = w_in[65536 + (z * 64 + c) * 256 + r];
    }
    else if (ii < 360448) v = w_in[131072 + (ii - 294912)];
    else                  v = w_out[ii - 360448];
    bf16 h = __float2bfloat16(v);
    g_wh[ii] = h;
    g_wl[ii] = __float2bfloat16(v - __bfloat162float(h));
}

// ---------------- K1 (R10-exact): stats + st rows + attention partials -----
__global__ __launch_bounds__(256) void k1_stats(
    const float* __restrict__ storage, const float* __restrict__ xmsg,
    float* __restrict__ out_st)
{
    __shared__ float sm[KS][DIM];
    __shared__ float qks[NH * DIM];
    __shared__ float xs[DIM];
    __shared__ float smask[KS];
    __shared__ float sred[8];
    __shared__ float sc[NH][KS];

    int b = blockIdx.x, tid = threadIdx.x;
    const float* row = storage + (long)b * KS * DIM;
    float vals[KS];
    #pragma unroll
    for (int j = 0; j < KS; j++) {
        vals[j] = row[j * DIM + tid];
        sm[j][tid] = vals[j];
    }
    xs[tid] = xmsg[(long)b * DIM + tid];
    #pragma unroll
    for (int h = 0; h < NH; h++)
        qks[h * DIM + tid] = g_qk[(long)b * 1024 + h * DIM + tid];
    __syncthreads();

    int w = tid >> 5, lane = tid & 31;
    for (int j = w; j < KS; j += 8) {
        const float4* sj = (const float4*)sm[j];
        float4 a = sj[lane], c = sj[lane + 32];
        float s = fabsf(a.x) + fabsf(a.y) + fabsf(a.z) + fabsf(a.w)
                + fabsf(c.x) + fabsf(c.y) + fabsf(c.z) + fabsf(c.w);
        s = warp_sum(s);
        if (lane == 0) smask[j] = (s > 0.f) ? 1.f : 0.f;
    }
    __syncthreads();

    float denom = EPSF;
    #pragma unroll
    for (int j = 0; j < KS; j++) denom += smask[j];

    int d = tid;
    float m = 0.f;
    #pragma unroll
    for (int j = 0; j < KS; j++) m += vals[j] * smask[j];
    float hmean = m / denom;
    float v = 0.f;
    #pragma unroll
    for (int j = 0; j < KS; j++) {
        float df = vals[j] - hmean;
        v += df * df * smask[j];
    }
    float hstd = sqrtf(v / denom);

    float xd = xs[d];
    float z = fabsf((xd - hmean) / (hstd + EPSF));
    float c = (z > 2.0f) ? 1.f : 0.f;
    c = warp_sum(c);
    if (lane == 0) sred[w] = c;
    __syncthreads();
    if (tid == 0) {
        float t = 0.f;
        #pragma unroll
        for (int i = 0; i < 8; i++) t += sred[i];
        g_stat[b] = t / (float)DIM;
    }

    store_split(g_mh + (long)b * 256 + d, g_ml + (long)b * 256 + d, hmean);

    float dec = 1.f;
    float* orow = out_st + (long)b * KS * DIM;
    #pragma unroll
    for (int jj = 0; jj < KS - 1; jj++) {
        float sv = vals[jj] * dec;
        vals[jj] = sv;
        sm[jj][d] = sv;
        orow[(jj + 1) * DIM + d] = sv;
        dec *= 0.95f;
    }
    __syncthreads();

    #pragma unroll
    for (int u = 0; u < 10; u++) {
        int id = w + u * 8;
        if (id < 76) {
            int h = id / 19, jj = id % 19;
            const float4* qh = (const float4*)(qks + h * DIM);
            const float4* sj = (const float4*)sm[jj];
            float4 a0 = qh[lane],      b0 = sj[lane];
            float4 a1 = qh[lane + 32], b1 = sj[lane + 32];
            float s = a0.x * b0.x + a0.y * b0.y + a0.z * b0.z + a0.w * b0.w
                    + a1.x * b1.x + a1.y * b1.y + a1.z * b1.z + a1.w * b1.w;
            s = warp_sum(s);
            if (lane == 0) sc[h][jj] = expf(s * 0.125f);
        } else {
            int h = id - 76;
            const float4* qh = (const float4*)(qks + h * DIM);
            const float4* xv = (const float4*)xs;
            float4 a0 = qh[lane],      b0 = xv[lane];
            float4 a1 = qh[lane + 32], b1 = xv[lane + 32];
            float s = a0.x * b0.x + a0.y * b0.y + a0.z * b0.z + a0.w * b0.w
                    + a1.x * b1.x + a1.y * b1.y + a1.z * b1.z + a1.w * b1.w;
            s = warp_sum(s);
            if (lane == 0) g_dot0[(long)b * NH + h] = s * 0.125f;
        }
    }
    __syncthreads();

    if (tid < NH) {
        float zz = 0.f;
        #pragma unroll
        for (int jj = 0; jj < KS - 1; jj++) zz += sc[tid][jj];
        g_Z[(long)b * NH + tid] = zz;
    }

    float acc[NH] = {0.f, 0.f, 0.f, 0.f};
    #pragma unroll
    for (int jj = 0; jj < KS - 1; jj++) {
        float sv = vals[jj];
        #pragma unroll
        for (int h = 0; h < NH; h++) acc[h] += sc[h][jj] * sv;
    }
    #pragma unroll
    for (int h = 0; h < NH; h++)
        g_N[(long)b * 1024 + h * DIM + d] = acc[h];
}

// ---------------- kf: anomaly + importance + st row0 + final attention -----
__global__ __launch_bounds__(256) void kf(
    const float* __restrict__ ad_b2, const float* __restrict__ imp_b2,
    const float* __restrict__ xmsg, float* __restrict__ out_st)
{
    __shared__ float se0[NH], sfac[NH];
    __shared__ float simp;
    int b = blockIdx.x, tid = threadIdx.x;

    if (tid == 0) {
        float d1 = ad_b2[0] + g_pad[0][b] + g_pad[1][b];
        float d2 = imp_b2[0] + g_pimp[0][b] + g_pimp[1][b]
                 + g_pimp[2][b] + g_pimp[3][b];
        float learned = 1.f / (1.f + expf(-d1));
        float anom = 0.5f * g_stat[b] + 0.5f * learned;
        float sp = fmaxf(d2, 0.f) + log1pf(expf(-fabsf(d2)));
        simp = sp * (1.f + anom);
    }
    __syncthreads();
    float imp = simp;
    if (tid < NH) {
        float e0 = expf(imp * g_dot0[(long)b * NH + tid]);
        se0[tid] = e0;
        sfac[tid] = 1.f / (g_Z[(long)b * NH + tid] + e0);
    }
    float x = xmsg[(long)b * 256 + tid];
    float st0 = x * imp;
    out_st[(long)b * KS * DIM + tid] = st0;
    __syncthreads();

    #pragma unroll
    for (int h = 0; h < NH; h++) {
        float s = (g_N[(long)b * 1024 + h * 256 + tid] + se0[h] * st0) * sfac[h];
        long o = (long)b * 1024 + h * 256 + tid;
        store_split(g_sh + o, g_sl + o, s);
    }
}

// ---------------- GEMM common pieces ---------------------------------------
#define PITCH 80
#define SZ_A 10240
#define SZ_B 5120
#define OFF_AL (SZ_A)
#define OFF_BH (2 * SZ_A)
#define OFF_BL (2 * SZ_A + SZ_B)
#define STAGE  (2 * SZ_A + 2 * SZ_B)   // 30720
#define SMEM_DYN (2 * STAGE)           // 61440

#define CP16(dst, src) asm volatile( \
    "cp.async.cg.shared.global [%0], [%1], 16;" :: "r"(dst), "l"(src))
#define CP_COMMIT() asm volatile("cp.async.commit_group;" ::: "memory")
#define CP_WAIT1()  asm volatile("cp.async.wait_group 1;" ::: "memory")
#define CP_WAIT0()  asm volatile("cp.async.wait_group 0;" ::: "memory")

__device__ __forceinline__ void ldmx4(uint32_t* r, uint32_t addr) {
    asm volatile("ldmatrix.sync.aligned.m8n8.x4.shared.b16 {%0,%1,%2,%3},[%4];"
                 : "=r"(r[0]), "=r"(r[1]), "=r"(r[2]), "=r"(r[3]) : "r"(addr));
}
__device__ __forceinline__ void mma16816(float* c, const uint32_t* a,
                                         const uint32_t* b) {
    asm volatile(
        "mma.sync.aligned.m16n8k16.row.col.f32.bf16.bf16.f32 "
        "{%0,%1,%2,%3},{%4,%5,%6,%7},{%8,%9},{%0,%1,%2,%3};"
        : "+f"(c[0]), "+f"(c[1]), "+f"(c[2]), "+f"(c[3])
        : "r"(a[0]), "r"(a[1]), "r"(a[2]), "r"(a[3]), "r"(b[0]), "r"(b[1]));
}
__device__ __forceinline__ uint32_t smem_u32(const void* p) {
    return (uint32_t)__cvta_generic_to_shared(p);
}

// ---------------- generic pipelined bf16x3 GEMM ----------------------------
// RED=1: epilogue computes per-row partial dot of relu(C) with w2 -> g_pimp
template<int ASEL, int KTOT, int SPLITK, int CBF, int ACT, int RED>
__global__ __launch_bounds__(256, 3) void gemm_pl(
    int lda, int aZ, int wOff, int ldb, int bZ,
    const float* __restrict__ bias, int biasZ,
    const float* __restrict__ w2,
    float* __restrict__ Cext, int ldc, int cZ)
{
    extern __shared__ __align__(128) char dsm[];
    __shared__ float sP[2][128];
    uint32_t sm0 = smem_u32(dsm);
    const int NST = 2;

    const bf16 *Ah, *Al;
    if (ASEL == 1 || ASEL == 2) { Ah = g_xh; Al = g_xl; }
    else if (ASEL == 4) { Ah = g_sh; Al = g_sl; }
    else                { Ah = g_ch; Al = g_cl; }
    float* Cf = Cext;

    int z  = blockIdx.z;
    int m0 = blockIdx.x * 128;
    int n0 = blockIdx.y * 64;
    long aOff = (long)aZ * z;
    long bOff = (long)wOff + (long)bZ * z;

    int tid = threadIdx.x;
    int warp = tid >> 5, lane = tid & 31;
    int wm = (warp >> 1) * 32, wn = (warp & 1) * 32;
    int lr = lane >> 2, lc = lane & 3;

    int arow = tid >> 1, acs = (tid & 1) * 2;
    int brow = tid >> 2, bcs = tid & 3;
    uint32_t aDst = arow * PITCH + acs * 16;
    uint32_t bDst = brow * PITCH + bcs * 16;
    long aRowOff = (long)(m0 + arow) * lda + aOff + acs * 8;
    long bSrc = bOff + (long)(n0 + brow) * ldb + bcs * 8;

    uint32_t aFrag = (uint32_t)((wm + (lane & 15)) * PITCH + (lane >> 4) * 16);
    uint32_t bFrag = (uint32_t)((wn + ((lane >> 4) << 3) + (lane & 7)) * PITCH
                                + ((lane >> 3) & 1) * 16);

    const int NCH = KTOT / 32;

    auto issue = [&](int ch, int st) {
        uint32_t sb = sm0 + st * STAGE;
        int c0 = ch * 32;
        const bf16* ah_ = Ah;
        const bf16* al_ = Al;
        int kk = c0;
        if (SPLITK < KTOT && c0 >= SPLITK) { ah_ = g_mh; al_ = g_ml; kk = c0 - SPLITK; }
        long ga = aRowOff + kk;
        CP16(sb + aDst,                ah_ + ga);
        CP16(sb + aDst + 16,           ah_ + ga + 8);
        CP16(sb + OFF_AL + aDst,       al_ + ga);
        CP16(sb + OFF_AL + aDst + 16,  al_ + ga + 8);
        long gb = bSrc + c0;
        CP16(sb + OFF_BH + bDst, g_wh + gb);
        CP16(sb + OFF_BL + bDst, g_wl + gb);
    };

    float acc[2][4][4];
    #pragma unroll
    for (int i = 0; i < 2; i++)
        #pragma unroll
        for (int j = 0; j < 4; j++)
            #pragma unroll
            for (int q = 0; q < 4; q++) acc[i][j][q] = 0.f;

    issue(0, 0);
    CP_COMMIT();

    #pragma unroll
    for (int ch = 0; ch < NCH; ch++) {
        if (ch + NST - 1 < NCH) {
            issue(ch + NST - 1, (ch + NST - 1) % NST);
            CP_COMMIT();
        }
        int pend = ((ch + NST < NCH) ? (ch + NST) : NCH) - ch - 1;
        if (pend >= 1) CP_WAIT1(); else CP_WAIT0();
        __syncthreads();

        uint32_t sb = sm0 + (ch % NST) * STAGE;
        #pragma unroll
        for (int ks = 0; ks < 2; ks++) {
            uint32_t kb = ks * 32;
            uint32_t ah[2][4], al[2][4], bh[2][4], bl[2][4];
            #pragma unroll
            for (int am = 0; am < 2; am++) {
                ldmx4(ah[am], sb + aFrag + am * (16 * PITCH) + kb);
                ldmx4(al[am], sb + OFF_AL + aFrag + am * (16 * PITCH) + kb);
            }
            #pragma unroll
            for (int anp = 0; anp < 2; anp++) {
                ldmx4(bh[anp], sb + OFF_BH + bFrag + anp * (16 * PITCH) + kb);
                ldmx4(bl[anp], sb + OFF_BL + bFrag + anp * (16 * PITCH) + kb);
            }
            #pragma unroll
            for (int am = 0; am < 2; am++)
                #pragma unroll
                for (int an = 0; an < 4; an++) {
                    const uint32_t* bph = &bh[an >> 1][(an & 1) * 2];
                    const uint32_t* bpl = &bl[an >> 1][(an & 1) * 2];
                    mma16816(acc[am][an], ah[am], bph);
                    mma16816(acc[am][an], ah[am], bpl);
                    mma16816(acc[am][an], al[am], bph);
                }
        }
        __syncthreads();
    }

    if (RED) {
        // relu + partial dot with w2 over this block's 64 columns
        float pa[2][2] = {{0.f, 0.f}, {0.f, 0.f}};
        #pragma unroll
        for (int am = 0; am < 2; am++)
            #pragma unroll
            for (int an = 0; an < 4; an++) {
                int col = n0 + wn + an * 8 + lc * 2;
                float b0 = bias[col], b1 = bias[col + 1];
                float v0 = fmaxf(acc[am][an][0] + b0, 0.f);
                float v1 = fmaxf(acc[am][an][1] + b1, 0.f);
                float v2 = fmaxf(acc[am][an][2] + b0, 0.f);
                float v3 = fmaxf(acc[am][an][3] + b1, 0.f);
                float w0 = w2[col], w1 = w2[col + 1];
                pa[am][0] += v0 * w0 + v1 * w1;
                pa[am][1] += v2 * w0 + v3 * w1;
            }
        #pragma unroll
        for (int am = 0; am < 2; am++)
            #pragma unroll
            for (int hf = 0; hf < 2; hf++) {
                float p = pa[am][hf];
                p += __shfl_xor_sync(0xffffffffu, p, 1);
                p += __shfl_xor_sync(0xffffffffu, p, 2);
                if (lc == 0) sP[warp & 1][wm + am * 16 + hf * 8 + lr] = p;
            }
        __syncthreads();
        if (tid < 128)
            g_pimp[blockIdx.y][(long)(m0 + tid)] = sP[0][tid] + sP[1][tid];
        return;
    }

    #pragma unroll
    for (int am = 0; am < 2; am++) {
        #pragma unroll
        for (int an = 0; an < 4; an++) {
            int row0 = m0 + wm + am * 16 + lr;
            int col  = n0 + wn + an * 8 + lc * 2;
            float b0 = 0.f, b1 = 0.f;
            if (bias) {
                b0 = bias[biasZ * z + col];
                b1 = bias[biasZ * z + col + 1];
            }
            float v0 = acc[am][an][0] + b0, v1 = acc[am][an][1] + b1;
            float v2 = acc[am][an][2] + b0, v3 = acc[am][an][3] + b1;
            if (ACT == 1) {
                v0 = fmaxf(v0, 0.f); v1 = fmaxf(v1, 0.f);
                v2 = fmaxf(v2, 0.f); v3 = fmaxf(v3, 0.f);
            }
            long off = (long)cZ * z + col;
            if (CBF) {
                long p0 = (long)row0 * ldc + off;
                long p1 = (long)(row0 + 8) * ldc + off;
                store_split(g_ch + p0, g_cl + p0, v0);
                store_split(g_ch + p0 + 1, g_cl + p0 + 1, v1);
                store_split(g_ch + p1, g_cl + p1, v2);
                store_split(g_ch + p1 + 1, g_cl + p1 + 1, v3);
            } else {
                *(float2*)(Cf + (long)row0 * ldc + off) = make_float2(v0, v1);
                *(float2*)(Cf + (long)(row0 + 8) * ldc + off) = make_float2(v2, v3);
            }
        }
    }
}

// ---------------- fused q + ad + qk kernel ---------------------------------
// grid (128, 6): ny<4 -> q head ny + in-block qk; ny>=4 -> ad partial dot.
#define QPITCH 144
#define OFF_QL 18432
#define OFF_B2 36864
__global__ __launch_bounds__(256, 2) void gemm_qfused(
    const float* __restrict__ bq, const float* __restrict__ adb,
    const float* __restrict__ ad_w2)
{
    extern __shared__ __align__(128) char dsm[];
    __shared__ float sP[2][128];
    uint32_t sm0 = smem_u32(dsm);

    int ny = blockIdx.y;
    int m0 = blockIdx.x * 128;
    int n0 = ny * 64;

    int tid = threadIdx.x;
    int warp = tid >> 5, lane = tid & 31;
    int wm = (warp >> 1) * 32, wn = (warp & 1) * 32;
    int lr = lane >> 2, lc = lane & 3;

    int arow = tid >> 1, acs = (tid & 1) * 2;
    int brow = tid >> 2, bcs = tid & 3;
    uint32_t aDst = arow * PITCH + acs * 16;
    uint32_t bDst = brow * PITCH + bcs * 16;
    long aRowOff = (long)(m0 + arow) * 256 + acs * 8;
    long bSrc = (long)(n0 + brow) * 256 + bcs * 8;

    uint32_t aFrag = (uint32_t)((wm + (lane & 15)) * PITCH + (lane >> 4) * 16);
    uint32_t bFrag = (uint32_t)((wn + ((lane >> 4) << 3) + (lane & 7)) * PITCH
                                + ((lane >> 3) & 1) * 16);

    auto issue = [&](int ch, int st) {
        uint32_t sb = sm0 + st * STAGE;
        int c0 = ch * 32;
        long ga = aRowOff + c0;
        CP16(sb + aDst,                g_xh + ga);
        CP16(sb + aDst + 16,           g_xh + ga + 8);
        CP16(sb + OFF_AL + aDst,       g_xl + ga);
        CP16(sb + OFF_AL + aDst + 16,  g_xl + ga + 8);
        long gb = bSrc + c0;
        CP16(sb + OFF_BH + bDst, g_wh + gb);
        CP16(sb + OFF_BL + bDst, g_wl + gb);
    };

    float acc[2][4][4];
    #pragma unroll
    for (int i = 0; i < 2; i++)
        #pragma unroll
        for (int j = 0; j < 4; j++)
            #pragma unroll
            for (int q = 0; q < 4; q++) acc[i][j][q] = 0.f;

    issue(0, 0);
    CP_COMMIT();
    #pragma unroll
    for (int ch = 0; ch < 8; ch++) {
        if (ch + 1 < 8) { issue(ch + 1, (ch + 1) & 1); CP_COMMIT(); }
        if (ch + 1 < 8) CP_WAIT1(); else CP_WAIT0();
        __syncthreads();
        uint32_t sb = sm0 + (ch & 1) * STAGE;
        #pragma unroll
        for (int ks = 0; ks < 2; ks++) {
            uint32_t kb = ks * 32;
            uint32_t ah[2][4], al[2][4], bh[2][4], bl[2][4];
            #pragma unroll
            for (int am = 0; am < 2; am++) {
                ldmx4(ah[am], sb + aFrag + am * (16 * PITCH) + kb);
                ldmx4(al[am], sb + OFF_AL + aFrag + am * (16 * PITCH) + kb);
            }
            #pragma unroll
            for (int anp = 0; anp < 2; anp++) {
                ldmx4(bh[anp], sb + OFF_BH + bFrag + anp * (16 * PITCH) + kb);
                ldmx4(bl[anp], sb + OFF_BL + bFrag + anp * (16 * PITCH) + kb);
            }
            #pragma unroll
            for (int am = 0; am < 2; am++)
                #pragma unroll
                for (int an = 0; an < 4; an++) {
                    const uint32_t* bph = &bh[an >> 1][(an & 1) * 2];
                    const uint32_t* bpl = &bl[an >> 1][(an & 1) * 2];
                    mma16816(acc[am][an], ah[am], bph);
                    mma16816(acc[am][an], ah[am], bpl);
                    mma16816(acc[am][an], al[am], bph);
                }
        }
        __syncthreads();
    }

    if (ny >= 4) {
        // ---- ad hidden: relu + partial dot with ad_w2 -> g_pad ----
        float pa[2][2] = {{0.f, 0.f}, {0.f, 0.f}};
        #pragma unroll
        for (int am = 0; am < 2; am++)
            #pragma unroll
            for (int an = 0; an < 4; an++) {
                int cc = n0 + wn + an * 8 + lc * 2 - 256;
                float b0 = adb[cc], b1 = adb[cc + 1];
                float v0 = fmaxf(acc[am][an][0] + b0, 0.f);
                float v1 = fmaxf(acc[am][an][1] + b1, 0.f);
                float v2 = fmaxf(acc[am][an][2] + b0, 0.f);
                float v3 = fmaxf(acc[am][an][3] + b1, 0.f);
                float w0 = ad_w2[cc], w1 = ad_w2[cc + 1];
                pa[am][0] += v0 * w0 + v1 * w1;
                pa[am][1] += v2 * w0 + v3 * w1;
            }
        #pragma unroll
        for (int am = 0; am < 2; am++)
            #pragma unroll
            for (int hf = 0; hf < 2; hf++) {
                float p = pa[am][hf];
                p += __shfl_xor_sync(0xffffffffu, p, 1);
                p += __shfl_xor_sync(0xffffffffu, p, 2);
                if (lc == 0) sP[warp & 1][wm + am * 16 + hf * 8 + lr] = p;
            }
        __syncthreads();
        if (tid < 128)
            g_pad[ny - 4][(long)(m0 + tid)] = sP[0][tid] + sP[1][tid];
        return;
    }

    // ---- stage A: q tile (bias added) -> smem bf16 hi/lo -------------------
    #pragma unroll
    for (int am = 0; am < 2; am++)
        #pragma unroll
        for (int an = 0; an < 4; an++) {
            int r0 = wm + am * 16 + lr;
            int ic = wn + an * 8 + lc * 2;
            float b0 = bq[n0 + ic], b1 = bq[n0 + ic + 1];
            float v0 = acc[am][an][0] + b0, v1 = acc[am][an][1] + b1;
            float v2 = acc[am][an][2] + b0, v3 = acc[am][an][3] + b1;
            store_split((bf16*)(dsm + r0 * QPITCH + ic * 2),
                        (bf16*)(dsm + OFF_QL + r0 * QPITCH + ic * 2), v0);
            store_split((bf16*)(dsm + r0 * QPITCH + ic * 2 + 2),
                        (bf16*)(dsm + OFF_QL + r0 * QPITCH + ic * 2 + 2), v1);
            store_split((bf16*)(dsm + (r0 + 8) * QPITCH + ic * 2),
                        (bf16*)(dsm + OFF_QL + (r0 + 8) * QPITCH + ic * 2), v2);
            store_split((bf16*)(dsm + (r0 + 8) * QPITCH + ic * 2 + 2),
                        (bf16*)(dsm + OFF_QL + (r0 + 8) * QPITCH + ic * 2 + 2), v3);
        }
    __syncthreads();

    // ---- stage B: qk[m, z*256 + sub*64 + n] = Q . wkT[z] -------------------
    int zz = ny;
    uint32_t aQ = sm0 + (uint32_t)((wm + (lane & 15)) * QPITCH + (lane >> 4) * 16);
    auto issueB = [&](int sub, int c) {
        uint32_t base = sm0 + OFF_B2 + c * (2 * SZ_B);
        long src = 229376 + (long)zz * 16384 + (long)(sub * 64 + brow) * 64
                 + c * 32 + bcs * 8;
        CP16(base + bDst, g_wh + src);
        CP16(base + SZ_B + bDst, g_wl + src);
    };

    for (int sub = 0; sub < 4; sub++) {
        if (sub) __syncthreads();
        issueB(sub, 0); CP_COMMIT();
        issueB(sub, 1); CP_COMMIT();

        float a2[2][4][4];
        #pragma unroll
        for (int i = 0; i < 2; i++)
            #pragma unroll
            for (int j = 0; j < 4; j++)
                #pragma unroll
                for (int q = 0; q < 4; q++) a2[i][j][q] = 0.f;

        #pragma unroll
        for (int c = 0; c < 2; c++) {
            if (c == 0) CP_WAIT1(); else CP_WAIT0();
            __syncthreads();
            uint32_t bb = sm0 + OFF_B2 + c * (2 * SZ_B);
            #pragma unroll
            for (int ks = 0; ks < 2; ks++) {
                uint32_t kbq = c * 64 + ks * 32;
                uint32_t kb = ks * 32;
                uint32_t ah[2][4], al[2][4], bh[2][4], bl[2][4];
                #pragma unroll
                for (int am = 0; am < 2; am++) {
                    ldmx4(ah[am], aQ + am * (16 * QPITCH) + kbq);
                    ldmx4(al[am], aQ + OFF_QL + am * (16 * QPITCH) + kbq);
                }
                #pragma unroll
                for (int anp = 0; anp < 2; anp++) {
                    ldmx4(bh[anp], bb + bFrag + anp * (16 * PITCH) + kb);
                    ldmx4(bl[anp], bb + SZ_B + bFrag + anp * (16 * PITCH) + kb);
                }
                #pragma unroll
                for (int am = 0; am < 2; am++)
                    #pragma unroll
                    for (int an = 0; an < 4; an++) {
                        const uint32_t* bph = &bh[an >> 1][(an & 1) * 2];
                        const uint32_t* bpl = &bl[an >> 1][(an & 1) * 2];
                        mma16816(a2[am][an], ah[am], bph);
                        mma16816(a2[am][an], ah[am], bpl);
                        mma16816(a2[am][an], al[am], bph);
                    }
            }
        }
        #pragma unroll
        for (int am = 0; am < 2; am++)
            #pragma unroll
            for (int an = 0; an < 4; an++) {
                int row0 = m0 + wm + am * 16 + lr;
                int col = zz * 256 + sub * 64 + wn + an * 8 + lc * 2;
                *(float2*)(g_qk + (long)row0 * 1024 + col) =
                    make_float2(a2[am][an][0], a2[am][an][1]);
                *(float2*)(g_qk + (long)(row0 + 8) * 1024 + col) =
                    make_float2(a2[am][an][2], a2[am][an][3]);
            }
    }
}

#define NOSPLIT (1 << 30)

// ---------------------------------------------------------------------------
extern "C" void kernel_launch(void* const* d_in, const int* in_sizes, int n_in,
                              void* d_out, int out_size) {
    const float* storage = (const float*)d_in[0];
    const float* x       = (const float*)d_in[1];
    const float* ad_w1   = (const float*)d_in[2];
    const float* ad_b1   = (const float*)d_in[3];
    const float* ad_w2   = (const float*)d_in[4];
    const float* ad_b2   = (const float*)d_in[5];
    const float* imp_w1  = (const float*)d_in[6];
    const float* imp_b1  = (const float*)d_in[7];
    const float* imp_w2  = (const float*)d_in[8];
    const float* imp_b2  = (const float*)d_in[9];
    const float* w_in    = (const float*)d_in[10];
    const float* b_in    = (const float*)d_in[11];
    const float* w_out   = (const float*)d_in[12];
    const float* b_out   = (const float*)d_in[13];

    float* st  = (float*)d_out;                       // [B,K,D]
    float* agg = st + (long)BATCH * KS * DIM;         // [B,D]

    cudaFuncSetAttribute(gemm_qfused,
                         cudaFuncAttributeMaxDynamicSharedMemorySize, SMEM_DYN);
    cudaFuncSetAttribute(gemm_pl<2, 512, 256, 0, 1, 1>,
                         cudaFuncAttributeMaxDynamicSharedMemorySize, SMEM_DYN);
    cudaFuncSetAttribute(gemm_pl<4, 256, NOSPLIT, 2, 0, 0>,
                         cudaFuncAttributeMaxDynamicSharedMemorySize, SMEM_DYN);
    cudaFuncSetAttribute(gemm_pl<5, 256, NOSPLIT, 0, 0, 0>,
                         cudaFuncAttributeMaxDynamicSharedMemorySize, SMEM_DYN);

    conv_all<<<(CONV_TOTAL + 255) / 256, 256>>>(ad_w1, imp_w1, w_in, w_out, x);
    // fused q (heads 0..3 + in-block qk -> g_qk) and ad partial dots (ny 4,5)
    gemm_qfused<<<dim3(128, 6, 1), 256, SMEM_DYN>>>(b_in, ad_b1, ad_w2);
    // stats + st rows 1..19 + attention partials (N1, Z1, dot0)
    k1_stats<<<BATCH, 256>>>(storage, x, st);
    // imp-MLP: relu([x|hmean] @ imp_w1^T + imp_b1) . imp_w2 -> g_pimp partials
    gemm_pl<2, 512, 256, 0, 1, 1><<<dim3(128, 4, 1), 256, SMEM_DYN>>>(
        256, 0, 98304, 512, 0, imp_b1, 0, imp_w2, nullptr, 256, 0);
    // anomaly + importance + st row0 + final weighted sums -> g_sh/g_sl
    kf<<<BATCH, 256>>>(ad_b2, imp_b2, x, st);
    // ctx[b, z*64+n] = wv_z[n,:] . s[b,z,:] + bv -> g_ch/g_cl [B,256]
    gemm_pl<4, 256, NOSPLIT, 2, 0, 0><<<dim3(128, 1, 4), 256, SMEM_DYN>>>(
        1024, 256, 294912, 256, 16384, b_in + 512, 64, nullptr, nullptr, 256, 64);
    // agg = ctx @ attn_out_w^T + attn_out_b -> d_out tail (fp32)
    gemm_pl<5, 256, NOSPLIT, 0, 0, 0><<<dim3(128, 4, 1), 256, SMEM_DYN>>>(
        256, 0, 360448, 256, 0, b_out, 0, nullptr, agg, 256, 0);
    (void)in_sizes; (void)n_in; (void)out_size;
}

// round 17
// speedup vs baseline: 1.1992x; 1.0516x over previous
#include <cuda_runtime.h>
#include <cuda_bf16.h>
#include <stdint.h>

#define BATCH 16384
#define KS 20
#define DIM 256
#define NH 4
#define EPSF 1e-8f

typedef __nv_bfloat16 bf16;

// ---------------- scratch (device globals; allocations are forbidden) ------
__device__ bf16 g_xh [(long)BATCH * 256], g_xl [(long)BATCH * 256];
__device__ bf16 g_mh [(long)BATCH * 256], g_ml [(long)BATCH * 256];  // hmean
__device__ bf16 g_sh [(long)BATCH * 1024], g_sl [(long)BATCH * 1024];
__device__ bf16 g_ch [(long)BATCH * 256], g_cl [(long)BATCH * 256];
#define W_TOTAL 425984
__device__ bf16 g_wh[W_TOTAL], g_wl[W_TOTAL];
__device__ float g_qk  [(long)BATCH * 1024];
__device__ float g_N   [(long)BATCH * 1024];
__device__ float g_Z   [(long)BATCH * NH];
__device__ float g_dot0[(long)BATCH * NH];
__device__ float g_stat[BATCH];
__device__ float g_pimp[4][BATCH];   // imp-MLP partial dots (per n-block)
__device__ float g_pad [2][BATCH];   // ad-MLP partial dots

__device__ __forceinline__ float warp_sum(float v) {
    #pragma unroll
    for (int o = 16; o; o >>= 1) v += __shfl_down_sync(0xffffffffu, v, o);
    return v;
}
__device__ __forceinline__ void store_split(bf16* ph, bf16* pl, float v) {
    bf16 h = __float2bfloat16(v);
    *ph = h;
    *pl = __float2bfloat16(v - __bfloat162float(h));
}

// ---------------- shared MMA helpers ---------------------------------------
__device__ __forceinline__ void ldmx4(uint32_t* r, uint32_t addr) {
    asm volatile("ldmatrix.sync.aligned.m8n8.x4.shared.b16 {%0,%1,%2,%3},[%4];"
                 : "=r"(r[0]), "=r"(r[1]), "=r"(r[2]), "=r"(r[3]) : "r"(addr));
}
__device__ __forceinline__ void mma16816(float* c, const uint32_t* a,
                                         const uint32_t* b) {
    asm volatile(
        "mma.sync.aligned.m16n8k16.row.col.f32.bf16.bf16.f32 "
        "{%0,%1,%2,%3},{%4,%5,%6,%7},{%8,%9},{%0,%1,%2,%3};"
        : "+f"(c[0]), "+f"(c[1]), "+f"(c[2]), "+f"(c[3])
        : "r"(a[0]), "r"(a[1]), "r"(a[2]), "r"(a[3]), "r"(b[0]), "r"(b[1]));
}
__device__ __forceinline__ uint32_t smem_u32(const void* p) {
    return (uint32_t)__cvta_generic_to_shared(p);
}

#define CP16(dst, src) asm volatile( \
    "cp.async.cg.shared.global [%0], [%1], 16;" :: "r"(dst), "l"(src))
#define CP_COMMIT() asm volatile("cp.async.commit_group;" ::: "memory")
#define CP_WAIT1()  asm volatile("cp.async.wait_group 1;" ::: "memory")
#define CP_WAIT0()  asm volatile("cp.async.wait_group 0;" ::: "memory")

// ---------------- conv: weights + x, one launch ----------------------------
//   [0,65536)        wq      [256][256]
//   [65536,98304)    ad_w1   [128][256]
//   [98304,229376)   imp_w1  [256][512]
//   [229376,294912)  wkT     [4][256 n][64 i]   (transposed)
//   [294912,360448)  wv      [256][256]
//   [360448,425984)  w_out   [256][256]
#define CONV_TOTAL (W_TOTAL + BATCH * 256)
__global__ __launch_bounds__(256) void conv_all(
    const float* __restrict__ ad_w1, const float* __restrict__ imp_w1,
    const float* __restrict__ w_in,  const float* __restrict__ w_out,
    const float* __restrict__ x)
{
    long i = (long)blockIdx.x * 256 + threadIdx.x;
    if (i >= CONV_TOTAL) return;
    if (i >= W_TOTAL) {
        long idx = i - W_TOTAL;
        store_split(g_xh + idx, g_xl + idx, x[idx]);
        return;
    }
    int ii = (int)i;
    float v;
    if (ii < 65536)       v = w_in[ii];
    else if (ii < 98304)  v = ad_w1[ii - 65536];
    else if (ii < 229376) v = imp_w1[ii - 98304];
    else if (ii < 294912) {
        int j = ii - 229376;
        int z = j >> 14, r = (j >> 6) & 255, c = j & 63;
        v = w_in[65536 + (z * 64 + c) * 256 + r];
    }
    else if (ii < 360448) v = w_in[131072 + (ii - 294912)];
    else                  v = w_out[ii - 360448];
    bf16 h = __float2bfloat16(v);
    g_wh[ii] = h;
    g_wl[ii] = __float2bfloat16(v - __bfloat162float(h));
}

// ---------------- K1: stats + st rows + MMA-based attention partials -------
// dynamic smem union layout (bytes):
//   [0, 16896)        B-hi tile: 32 rows x 528B (rows 0..18 decayed, 19 = x)
//   [16896, 33792)    B-lo tile
//   [33792, 42240)    A-hi tile: 16 rows x 528B (rows 0..3 = qk)   / sC after
//   [42240, 50688)    A-lo tile
// phase 1: bytes [0, 20480) hold sm[20][256] fp32 (dead after mask)
#define TP 528
#define KB_H 0
#define KB_L 16896
#define KA_H 33792
#define KA_L 42240
#define K1_SMEM 50688

__global__ __launch_bounds__(256) void k1_stats(
    const float* __restrict__ storage, const float* __restrict__ xmsg,
    float* __restrict__ out_st)
{
    extern __shared__ __align__(16) char uS[];
    __shared__ float smask[KS];
    __shared__ float sred[8];
    __shared__ float sc[NH][KS];

    float (*sm)[DIM] = (float(*)[DIM])uS;
    int b = blockIdx.x, tid = threadIdx.x;
    int w = tid >> 5, lane = tid & 31;
    const float* row = storage + (long)b * KS * DIM;
    float vals[KS];
    #pragma unroll
    for (int j = 0; j < KS; j++) {
        vals[j] = row[j * DIM + tid];
        sm[j][tid] = vals[j];
    }
    float xd = xmsg[(long)b * DIM + tid];
    float qkreg[NH];
    #pragma unroll
    for (int h = 0; h < NH; h++)
        qkreg[h] = g_qk[(long)b * 1024 + h * 256 + tid];
    __syncthreads();

    // mask: float4 scans of raw rows
    for (int j = w; j < KS; j += 8) {
        const float4* sj = (const float4*)sm[j];
        float4 a = sj[lane], c = sj[lane + 32];
        float s = fabsf(a.x) + fabsf(a.y) + fabsf(a.z) + fabsf(a.w)
                + fabsf(c.x) + fabsf(c.y) + fabsf(c.z) + fabsf(c.w);
        s = warp_sum(s);
        if (lane == 0) smask[j] = (s > 0.f) ? 1.f : 0.f;
    }
    __syncthreads();                    // sm dead after this point

    float denom = EPSF;
    #pragma unroll
    for (int j = 0; j < KS; j++) denom += smask[j];

    int d = tid;
    float m = 0.f;
    #pragma unroll
    for (int j = 0; j < KS; j++) m += vals[j] * smask[j];
    float hmean = m / denom;
    float v = 0.f;
    #pragma unroll
    for (int j = 0; j < KS; j++) {
        float df = vals[j] - hmean;
        v += df * df * smask[j];
    }
    float hstd = sqrtf(v / denom);

    float z = fabsf((xd - hmean) / (hstd + EPSF));
    float c = (z > 2.0f) ? 1.f : 0.f;
    c = warp_sum(c);
    if (lane == 0) sred[w] = c;
    __syncthreads();
    if (tid == 0) {
        float t = 0.f;
        #pragma unroll
        for (int i = 0; i < 8; i++) t += sred[i];
        g_stat[b] = t / (float)DIM;
    }

    store_split(g_mh + (long)b * 256 + d, g_ml + (long)b * 256 + d, hmean);

    // decay into regs + st rows 1..19 to global
    {
        float* orow = out_st + (long)b * KS * DIM;
        float dec = 1.f;
        #pragma unroll
        for (int jj = 0; jj < KS - 1; jj++) {
            float sv = vals[jj] * dec;
            vals[jj] = sv;
            orow[(jj + 1) * DIM + d] = sv;
            dec *= 0.95f;
        }
    }

    // conversion: decayed rows (+x) -> B tiles; qk -> A tiles (bf16 hi/lo)
    {
        bf16* BH = (bf16*)(uS + KB_H);
        bf16* BL = (bf16*)(uS + KB_L);
        bf16* AH = (bf16*)(uS + KA_H);
        bf16* AL = (bf16*)(uS + KA_L);
        #pragma unroll
        for (int j = 0; j < KS - 1; j++)
            store_split(BH + j * 264 + d, BL + j * 264 + d, vals[j]);
        store_split(BH + 19 * 264 + d, BL + 19 * 264 + d, xd);
        #pragma unroll
        for (int h = 0; h < NH; h++)
            store_split(AH + h * 264 + d, AL + h * 264 + d, qkreg[h]);
    }
    __syncthreads();

    // MMA: scores C[4 x 20] = QK[4 x 256] . ST^T ; warp w does ksteps w, w+8
    float cf[3][4];
    #pragma unroll
    for (int a = 0; a < 3; a++)
        #pragma unroll
        for (int q = 0; q < 4; q++) cf[a][q] = 0.f;
    {
        uint32_t base = smem_u32(uS);
        uint32_t aoff = (lane & 15) * TP + ((lane >> 4) * 16);
        uint32_t brow = (((lane >> 4) << 3) + (lane & 7)) * TP
                      + (((lane >> 3) & 1) * 16);
        #pragma unroll
        for (int s2 = 0; s2 < 2; s2++) {
            uint32_t kb = (uint32_t)(w + s2 * 8) * 32;
            uint32_t ah[4], al[4], bAh[4], bBh[4], bAl[4], bBl[4];
            ldmx4(ah, base + KA_H + aoff + kb);
            ldmx4(al, base + KA_L + aoff + kb);
            ldmx4(bAh, base + KB_H + brow + kb);
            ldmx4(bBh, base + KB_H + 16 * TP + brow + kb);
            ldmx4(bAl, base + KB_L + brow + kb);
            ldmx4(bBl, base + KB_L + 16 * TP + brow + kb);
            mma16816(cf[0], ah, &bAh[0]);
            mma16816(cf[1], ah, &bAh[2]);
            mma16816(cf[2], ah, &bBh[0]);
            mma16816(cf[0], ah, &bAl[0]);
            mma16816(cf[1], ah, &bAl[2]);
            mma16816(cf[2], ah, &bBl[0]);
            mma16816(cf[0], al, &bAh[0]);
            mma16816(cf[1], al, &bAh[2]);
            mma16816(cf[2], al, &bBh[0]);
        }
    }
    __syncthreads();                    // A tiles dead; reuse as sC
    float* sC = (float*)(uS + KA_H);
    if (lane < 16) {
        int r = lane >> 2, cb = (lane & 3) * 2;
        #pragma unroll
        for (int a = 0; a < 3; a++) {
            sC[w * 96 + r * 24 + a * 8 + cb]     = cf[a][0];
            sC[w * 96 + r * 24 + a * 8 + cb + 1] = cf[a][1];
        }
    }
    __syncthreads();
    if (tid < 80) {
        int h = tid / 20, j = tid % 20;
        float s = 0.f;
        #pragma unroll
        for (int ww = 0; ww < 8; ww++) s += sC[ww * 96 + h * 24 + j];
        s *= 0.125f;
        if (j < 19) sc[h][j] = expf(s);
        else g_dot0[(long)b * NH + h] = s;
    }
    __syncthreads();

    if (tid < NH) {
        float zz = 0.f;
        #pragma unroll
        for (int jj = 0; jj < KS - 1; jj++) zz += sc[tid][jj];
        g_Z[(long)b * NH + tid] = zz;
    }

    // N[h][d] = sum_jj e[h][jj] * decayed[jj][d]  (reconstruct from hi+lo)
    {
        const bf16* BH = (const bf16*)(uS + KB_H);
        const bf16* BL = (const bf16*)(uS + KB_L);
        float acc[NH] = {0.f, 0.f, 0.f, 0.f};
        #pragma unroll
        for (int jj = 0; jj < KS - 1; jj++) {
            float sv = __bfloat162float(BH[jj * 264 + d])
                     + __bfloat162float(BL[jj * 264 + d]);
            #pragma unroll
            for (int h = 0; h < NH; h++) acc[h] += sc[h][jj] * sv;
        }
        #pragma unroll
        for (int h = 0; h < NH; h++)
            g_N[(long)b * 1024 + h * DIM + d] = acc[h];
    }
}

// ---------------- kf: anomaly + importance + st row0 + final attention -----
__global__ __launch_bounds__(256) void kf(
    const float* __restrict__ ad_b2, const float* __restrict__ imp_b2,
    const float* __restrict__ xmsg, float* __restrict__ out_st)
{
    __shared__ float se0[NH], sfac[NH];
    __shared__ float simp;
    int b = blockIdx.x, tid = threadIdx.x;

    if (tid == 0) {
        float d1 = ad_b2[0] + g_pad[0][b] + g_pad[1][b];
        float d2 = imp_b2[0] + g_pimp[0][b] + g_pimp[1][b]
                 + g_pimp[2][b] + g_pimp[3][b];
        float learned = 1.f / (1.f + expf(-d1));
        float anom = 0.5f * g_stat[b] + 0.5f * learned;
        float sp = fmaxf(d2, 0.f) + log1pf(expf(-fabsf(d2)));
        simp = sp * (1.f + anom);
    }
    __syncthreads();
    float imp = simp;
    if (tid < NH) {
        float e0 = expf(imp * g_dot0[(long)b * NH + tid]);
        se0[tid] = e0;
        sfac[tid] = 1.f / (g_Z[(long)b * NH + tid] + e0);
    }
    float x = xmsg[(long)b * 256 + tid];
    float st0 = x * imp;
    out_st[(long)b * KS * DIM + tid] = st0;
    __syncthreads();

    #pragma unroll
    for (int h = 0; h < NH; h++) {
        float s = (g_N[(long)b * 1024 + h * 256 + tid] + se0[h] * st0) * sfac[h];
        long o = (long)b * 1024 + h * 256 + tid;
        store_split(g_sh + o, g_sl + o, s);
    }
}

// ---------------- GEMM common pieces ---------------------------------------
#define PITCH 80
#define SZ_A 10240
#define SZ_B 5120
#define OFF_AL (SZ_A)
#define OFF_BH (2 * SZ_A)
#define OFF_BL (2 * SZ_A + SZ_B)
#define STAGE  (2 * SZ_A + 2 * SZ_B)   // 30720
#define SMEM_DYN (2 * STAGE)           // 61440

// ---------------- generic pipelined bf16x3 GEMM ----------------------------
// RED=1: epilogue computes per-row partial dot of relu(C) with w2 -> g_pimp
template<int ASEL, int KTOT, int SPLITK, int CBF, int ACT, int RED>
__global__ __launch_bounds__(256, 3) void gemm_pl(
    int lda, int aZ, int wOff, int ldb, int bZ,
    const float* __restrict__ bias, int biasZ,
    const float* __restrict__ w2,
    float* __restrict__ Cext, int ldc, int cZ)
{
    extern __shared__ __align__(128) char dsm[];
    __shared__ float sP[2][128];
    uint32_t sm0 = smem_u32(dsm);
    const int NST = 2;

    const bf16 *Ah, *Al;
    if (ASEL == 1 || ASEL == 2) { Ah = g_xh; Al = g_xl; }
    else if (ASEL == 4) { Ah = g_sh; Al = g_sl; }
    else                { Ah = g_ch; Al = g_cl; }
    float* Cf = Cext;

    int z  = blockIdx.z;
    int m0 = blockIdx.x * 128;
    int n0 = blockIdx.y * 64;
    long aOff = (long)aZ * z;
    long bOff = (long)wOff + (long)bZ * z;

    int tid = threadIdx.x;
    int warp = tid >> 5, lane = tid & 31;
    int wm = (warp >> 1) * 32, wn = (warp & 1) * 32;
    int lr = lane >> 2, lc = lane & 3;

    int arow = tid >> 1, acs = (tid & 1) * 2;
    int brow = tid >> 2, bcs = tid & 3;
    uint32_t aDst = arow * PITCH + acs * 16;
    uint32_t bDst = brow * PITCH + bcs * 16;
    long aRowOff = (long)(m0 + arow) * lda + aOff + acs * 8;
    long bSrc = bOff + (long)(n0 + brow) * ldb + bcs * 8;

    uint32_t aFrag = (uint32_t)((wm + (lane & 15)) * PITCH + (lane >> 4) * 16);
    uint32_t bFrag = (uint32_t)((wn + ((lane >> 4) << 3) + (lane & 7)) * PITCH
                                + ((lane >> 3) & 1) * 16);

    const int NCH = KTOT / 32;

    auto issue = [&](int ch, int st) {
        uint32_t sb = sm0 + st * STAGE;
        int c0 = ch * 32;
        const bf16* ah_ = Ah;
        const bf16* al_ = Al;
        int kk = c0;
        if (SPLITK < KTOT && c0 >= SPLITK) { ah_ = g_mh; al_ = g_ml; kk = c0 - SPLITK; }
        long ga = aRowOff + kk;
        CP16(sb + aDst,                ah_ + ga);
        CP16(sb + aDst + 16,           ah_ + ga + 8);
        CP16(sb + OFF_AL + aDst,       al_ + ga);
        CP16(sb + OFF_AL + aDst + 16,  al_ + ga + 8);
        long gb = bSrc + c0;
        CP16(sb + OFF_BH + bDst, g_wh + gb);
        CP16(sb + OFF_BL + bDst, g_wl + gb);
    };

    float acc[2][4][4];
    #pragma unroll
    for (int i = 0; i < 2; i++)
        #pragma unroll
        for (int j = 0; j < 4; j++)
            #pragma unroll
            for (int q = 0; q < 4; q++) acc[i][j][q] = 0.f;

    issue(0, 0);
    CP_COMMIT();

    #pragma unroll
    for (int ch = 0; ch < NCH; ch++) {
        if (ch + NST - 1 < NCH) {
            issue(ch + NST - 1, (ch + NST - 1) % NST);
            CP_COMMIT();
        }
        int pend = ((ch + NST < NCH) ? (ch + NST) : NCH) - ch - 1;
        if (pend >= 1) CP_WAIT1(); else CP_WAIT0();
        __syncthreads();

        uint32_t sb = sm0 + (ch % NST) * STAGE;
        #pragma unroll
        for (int ks = 0; ks < 2; ks++) {
            uint32_t kb = ks * 32;
            uint32_t ah[2][4], al[2][4], bh[2][4], bl[2][4];
            #pragma unroll
            for (int am = 0; am < 2; am++) {
                ldmx4(ah[am], sb + aFrag + am * (16 * PITCH) + kb);
                ldmx4(al[am], sb + OFF_AL + aFrag + am * (16 * PITCH) + kb);
            }
            #pragma unroll
            for (int anp = 0; anp < 2; anp++) {
                ldmx4(bh[anp], sb + OFF_BH + bFrag + anp * (16 * PITCH) + kb);
                ldmx4(bl[anp], sb + OFF_BL + bFrag + anp * (16 * PITCH) + kb);
            }
            #pragma unroll
            for (int am = 0; am < 2; am++)
                #pragma unroll
                for (int an = 0; an < 4; an++) {
                    const uint32_t* bph = &bh[an >> 1][(an & 1) * 2];
                    const uint32_t* bpl = &bl[an >> 1][(an & 1) * 2];
                    mma16816(acc[am][an], ah[am], bph);
                    mma16816(acc[am][an], ah[am], bpl);
                    mma16816(acc[am][an], al[am], bph);
                }
        }
        __syncthreads();
    }

    if (RED) {
        float pa[2][2] = {{0.f, 0.f}, {0.f, 0.f}};
        #pragma unroll
        for (int am = 0; am < 2; am++)
            #pragma unroll
            for (int an = 0; an < 4; an++) {
                int col = n0 + wn + an * 8 + lc * 2;
                float b0 = bias[col], b1 = bias[col + 1];
                float v0 = fmaxf(acc[am][an][0] + b0, 0.f);
                float v1 = fmaxf(acc[am][an][1] + b1, 0.f);
                float v2 = fmaxf(acc[am][an][2] + b0, 0.f);
                float v3 = fmaxf(acc[am][an][3] + b1, 0.f);
                float w0 = w2[col], w1 = w2[col + 1];
                pa[am][0] += v0 * w0 + v1 * w1;
                pa[am][1] += v2 * w0 + v3 * w1;
            }
        #pragma unroll
        for (int am = 0; am < 2; am++)
            #pragma unroll
            for (int hf = 0; hf < 2; hf++) {
                float p = pa[am][hf];
                p += __shfl_xor_sync(0xffffffffu, p, 1);
                p += __shfl_xor_sync(0xffffffffu, p, 2);
                if (lc == 0) sP[warp & 1][wm + am * 16 + hf * 8 + lr] = p;
            }
        __syncthreads();
        if (tid < 128)
            g_pimp[blockIdx.y][(long)(m0 + tid)] = sP[0][tid] + sP[1][tid];
        return;
    }

    #pragma unroll
    for (int am = 0; am < 2; am++) {
        #pragma unroll
        for (int an = 0; an < 4; an++) {
            int row0 = m0 + wm + am * 16 + lr;
            int col  = n0 + wn + an * 8 + lc * 2;
            float b0 = 0.f, b1 = 0.f;
            if (bias) {
                b0 = bias[biasZ * z + col];
                b1 = bias[biasZ * z + col + 1];
            }
            float v0 = acc[am][an][0] + b0, v1 = acc[am][an][1] + b1;
            float v2 = acc[am][an][2] + b0, v3 = acc[am][an][3] + b1;
            if (ACT == 1) {
                v0 = fmaxf(v0, 0.f); v1 = fmaxf(v1, 0.f);
                v2 = fmaxf(v2, 0.f); v3 = fmaxf(v3, 0.f);
            }
            long off = (long)cZ * z + col;
            if (CBF) {
                long p0 = (long)row0 * ldc + off;
                long p1 = (long)(row0 + 8) * ldc + off;
                store_split(g_ch + p0, g_cl + p0, v0);
                store_split(g_ch + p0 + 1, g_cl + p0 + 1, v1);
                store_split(g_ch + p1, g_cl + p1, v2);
                store_split(g_ch + p1 + 1, g_cl + p1 + 1, v3);
            } else {
                *(float2*)(Cf + (long)row0 * ldc + off) = make_float2(v0, v1);
                *(float2*)(Cf + (long)(row0 + 8) * ldc + off) = make_float2(v2, v3);
            }
        }
    }
}

// ---------------- fused q + ad + qk kernel ---------------------------------
#define QPITCH 144
#define OFF_QL 18432
#define OFF_B2 36864
__global__ __launch_bounds__(256, 2) void gemm_qfused(
    const float* __restrict__ bq, const float* __restrict__ adb,
    const float* __restrict__ ad_w2)
{
    extern __shared__ __align__(128) char dsm[];
    __shared__ float sP[2][128];
    uint32_t sm0 = smem_u32(dsm);

    int ny = blockIdx.y;
    int m0 = blockIdx.x * 128;
    int n0 = ny * 64;

    int tid = threadIdx.x;
    int warp = tid >> 5, lane = tid & 31;
    int wm = (warp >> 1) * 32, wn = (warp & 1) * 32;
    int lr = lane >> 2, lc = lane & 3;

    int arow = tid >> 1, acs = (tid & 1) * 2;
    int brow = tid >> 2, bcs = tid & 3;
    uint32_t aDst = arow * PITCH + acs * 16;
    uint32_t bDst = brow * PITCH + bcs * 16;
    long aRowOff = (long)(m0 + arow) * 256 + acs * 8;
    long bSrc = (long)(n0 + brow) * 256 + bcs * 8;

    uint32_t aFrag = (uint32_t)((wm + (lane & 15)) * PITCH + (lane >> 4) * 16);
    uint32_t bFrag = (uint32_t)((wn + ((lane >> 4) << 3) + (lane & 7)) * PITCH
                                + ((lane >> 3) & 1) * 16);

    auto issue = [&](int ch, int st) {
        uint32_t sb = sm0 + st * STAGE;
        int c0 = ch * 32;
        long ga = aRowOff + c0;
        CP16(sb + aDst,                g_xh + ga);
        CP16(sb + aDst + 16,           g_xh + ga + 8);
        CP16(sb + OFF_AL + aDst,       g_xl + ga);
        CP16(sb + OFF_AL + aDst + 16,  g_xl + ga + 8);
        long gb = bSrc + c0;
        CP16(sb + OFF_BH + bDst, g_wh + gb);
        CP16(sb + OFF_BL + bDst, g_wl + gb);
    };

    float acc[2][4][4];
    #pragma unroll
    for (int i = 0; i < 2; i++)
        #pragma unroll
        for (int j = 0; j < 4; j++)
            #pragma unroll
            for (int q = 0; q < 4; q++) acc[i][j][q] = 0.f;

    issue(0, 0);
    CP_COMMIT();
    #pragma unroll
    for (int ch = 0; ch < 8; ch++) {
        if (ch + 1 < 8) { issue(ch + 1, (ch + 1) & 1); CP_COMMIT(); }
        if (ch + 1 < 8) CP_WAIT1(); else CP_WAIT0();
        __syncthreads();
        uint32_t sb = sm0 + (ch & 1) * STAGE;
        #pragma unroll
        for (int ks = 0; ks < 2; ks++) {
            uint32_t kb = ks * 32;
            uint32_t ah[2][4], al[2][4], bh[2][4], bl[2][4];
            #pragma unroll
            for (int am = 0; am < 2; am++) {
                ldmx4(ah[am], sb + aFrag + am * (16 * PITCH) + kb);
                ldmx4(al[am], sb + OFF_AL + aFrag + am * (16 * PITCH) + kb);
            }
            #pragma unroll
            for (int anp = 0; anp < 2; anp++) {
                ldmx4(bh[anp], sb + OFF_BH + bFrag + anp * (16 * PITCH) + kb);
                ldmx4(bl[anp], sb + OFF_BL + bFrag + anp * (16 * PITCH) + kb);
            }
            #pragma unroll
            for (int am = 0; am < 2; am++)
                #pragma unroll
                for (int an = 0; an < 4; an++) {
                    const uint32_t* bph = &bh[an >> 1][(an & 1) * 2];
                    const uint32_t* bpl = &bl[an >> 1][(an & 1) * 2];
                    mma16816(acc[am][an], ah[am], bph);
                    mma16816(acc[am][an], ah[am], bpl);
                    mma16816(acc[am][an], al[am], bph);
                }
        }
        __syncthreads();
    }

    if (ny >= 4) {
        float pa[2][2] = {{0.f, 0.f}, {0.f, 0.f}};
        #pragma unroll
        for (int am = 0; am < 2; am++)
            #pragma unroll
            for (int an = 0; an < 4; an++) {
                int cc = n0 + wn + an * 8 + lc * 2 - 256;
                float b0 = adb[cc], b1 = adb[cc + 1];
                float v0 = fmaxf(acc[am][an][0] + b0, 0.f);
                float v1 = fmaxf(acc[am][an][1] + b1, 0.f);
                float v2 = fmaxf(acc[am][an][2] + b0, 0.f);
                float v3 = fmaxf(acc[am][an][3] + b1, 0.f);
                float w0 = ad_w2[cc], w1 = ad_w2[cc + 1];
                pa[am][0] += v0 * w0 + v1 * w1;
                pa[am][1] += v2 * w0 + v3 * w1;
            }
        #pragma unroll
        for (int am = 0; am < 2; am++)
            #pragma unroll
            for (int hf = 0; hf < 2; hf++) {
                float p = pa[am][hf];
                p += __shfl_xor_sync(0xffffffffu, p, 1);
                p += __shfl_xor_sync(0xffffffffu, p, 2);
                if (lc == 0) sP[warp & 1][wm + am * 16 + hf * 8 + lr] = p;
            }
        __syncthreads();
        if (tid < 128)
            g_pad[ny - 4][(long)(m0 + tid)] = sP[0][tid] + sP[1][tid];
        return;
    }

    // stage A: q tile (bias added) -> smem bf16 hi/lo
    #pragma unroll
    for (int am = 0; am < 2; am++)
        #pragma unroll
        for (int an = 0; an < 4; an++) {
            int r0 = wm + am * 16 + lr;
            int ic = wn + an * 8 + lc * 2;
            float b0 = bq[n0 + ic], b1 = bq[n0 + ic + 1];
            float v0 = acc[am][an][0] + b0, v1 = acc[am][an][1] + b1;
            float v2 = acc[am][an][2] + b0, v3 = acc[am][an][3] + b1;
            store_split((bf16*)(dsm + r0 * QPITCH + ic * 2),
                        (bf16*)(dsm + OFF_QL + r0 * QPITCH + ic * 2), v0);
            store_split((bf16*)(dsm + r0 * QPITCH + ic * 2 + 2),
                        (bf16*)(dsm + OFF_QL + r0 * QPITCH + ic * 2 + 2), v1);
            store_split((bf16*)(dsm + (r0 + 8) * QPITCH + ic * 2),
                        (bf16*)(dsm + OFF_QL + (r0 + 8) * QPITCH + ic * 2), v2);
            store_split((bf16*)(dsm + (r0 + 8) * QPITCH + ic * 2 + 2),
                        (bf16*)(dsm + OFF_QL + (r0 + 8) * QPITCH + ic * 2 + 2), v3);
        }
    __syncthreads();

    // stage B: qk[m, z*256 + sub*64 + n] = Q . wkT[z]
    int zz = ny;
    uint32_t aQ = sm0 + (uint32_t)((wm + (lane & 15)) * QPITCH + (lane >> 4) * 16);
    auto issueB = [&](int sub, int c) {
        uint32_t base = sm0 + OFF_B2 + c * (2 * SZ_B);
        long src = 229376 + (long)zz * 16384 + (long)(sub * 64 + brow) * 64
                 + c * 32 + bcs * 8;
        CP16(base + bDst, g_wh + src);
        CP16(base + SZ_B + bDst, g_wl + src);
    };

    for (int sub = 0; sub < 4; sub++) {
        if (sub) __syncthreads();
        issueB(sub, 0); CP_COMMIT();
        issueB(sub, 1); CP_COMMIT();

        float a2[2][4][4];
        #pragma unroll
        for (int i = 0; i < 2; i++)
            #pragma unroll
            for (int j = 0; j < 4; j++)
                #pragma unroll
                for (int q = 0; q < 4; q++) a2[i][j][q] = 0.f;

        #pragma unroll
        for (int c = 0; c < 2; c++) {
            if (c == 0) CP_WAIT1(); else CP_WAIT0();
            __syncthreads();
            uint32_t bb = sm0 + OFF_B2 + c * (2 * SZ_B);
            #pragma unroll
            for (int ks = 0; ks < 2; ks++) {
                uint32_t kbq = c * 64 + ks * 32;
                uint32_t kb = ks * 32;
                uint32_t ah[2][4], al[2][4], bh[2][4], bl[2][4];
                #pragma unroll
                for (int am = 0; am < 2; am++) {
                    ldmx4(ah[am], aQ + am * (16 * QPITCH) + kbq);
                    ldmx4(al[am], aQ + OFF_QL + am * (16 * QPITCH) + kbq);
                }
                #pragma unroll
                for (int anp = 0; anp < 2; anp++) {
                    ldmx4(bh[anp], bb + bFrag + anp * (16 * PITCH) + kb);
                    ldmx4(bl[anp], bb + SZ_B + bFrag + anp * (16 * PITCH) + kb);
                }
                #pragma unroll
                for (int am = 0; am < 2; am++)
                    #pragma unroll
                    for (int an = 0; an < 4; an++) {
                        const uint32_t* bph = &bh[an >> 1][(an & 1) * 2];
                        const uint32_t* bpl = &bl[an >> 1][(an & 1) * 2];
                        mma16816(a2[am][an], ah[am], bph);
                        mma16816(a2[am][an], ah[am], bpl);
                        mma16816(a2[am][an], al[am], bph);
                    }
            }
        }
        #pragma unroll
        for (int am = 0; am < 2; am++)
            #pragma unroll
            for (int an = 0; an < 4; an++) {
                int row0 = m0 + wm + am * 16 + lr;
                int col = zz * 256 + sub * 64 + wn + an * 8 + lc * 2;
                *(float2*)(g_qk + (long)row0 * 1024 + col) =
                    make_float2(a2[am][an][0], a2[am][an][1]);
                *(float2*)(g_qk + (long)(row0 + 8) * 1024 + col) =
                    make_float2(a2[am][an][2], a2[am][an][3]);
            }
    }
}

#define NOSPLIT (1 << 30)

// ---------------------------------------------------------------------------
extern "C" void kernel_launch(void* const* d_in, const int* in_sizes, int n_in,
                              void* d_out, int out_size) {
    const float* storage = (const float*)d_in[0];
    const float* x       = (const float*)d_in[1];
    const float* ad_w1   = (const float*)d_in[2];
    const float* ad_b1   = (const float*)d_in[3];
    const float* ad_w2   = (const float*)d_in[4];
    const float* ad_b2   = (const float*)d_in[5];
    const float* imp_w1  = (const float*)d_in[6];
    const float* imp_b1  = (const float*)d_in[7];
    const float* imp_w2  = (const float*)d_in[8];
    const float* imp_b2  = (const float*)d_in[9];
    const float* w_in    = (const float*)d_in[10];
    const float* b_in    = (const float*)d_in[11];
    const float* w_out   = (const float*)d_in[12];
    const float* b_out   = (const float*)d_in[13];

    float* st  = (float*)d_out;                       // [B,K,D]
    float* agg = st + (long)BATCH * KS * DIM;         // [B,D]

    cudaFuncSetAttribute(k1_stats,
                         cudaFuncAttributeMaxDynamicSharedMemorySize, K1_SMEM);
    cudaFuncSetAttribute(gemm_qfused,
                         cudaFuncAttributeMaxDynamicSharedMemorySize, SMEM_DYN);
    cudaFuncSetAttribute(gemm_pl<2, 512, 256, 0, 1, 1>,
                         cudaFuncAttributeMaxDynamicSharedMemorySize, SMEM_DYN);
    cudaFuncSetAttribute(gemm_pl<4, 256, NOSPLIT, 2, 0, 0>,
                         cudaFuncAttributeMaxDynamicSharedMemorySize, SMEM_DYN);
    cudaFuncSetAttribute(gemm_pl<5, 256, NOSPLIT, 0, 0, 0>,
                         cudaFuncAttributeMaxDynamicSharedMemorySize, SMEM_DYN);

    conv_all<<<(CONV_TOTAL + 255) / 256, 256>>>(ad_w1, imp_w1, w_in, w_out, x);
    // fused q (heads 0..3 + in-block qk -> g_qk) and ad partial dots (ny 4,5)
    gemm_qfused<<<dim3(128, 6, 1), 256, SMEM_DYN>>>(b_in, ad_b1, ad_w2);
    // stats + st rows 1..19 + attention partials (N1, Z1, dot0) via MMA
    k1_stats<<<BATCH, 256, K1_SMEM>>>(storage, x, st);
    // imp-MLP: relu([x|hmean] @ imp_w1^T + imp_b1) . imp_w2 -> g_pimp partials
    gemm_pl<2, 512, 256, 0, 1, 1><<<dim3(128, 4, 1), 256, SMEM_DYN>>>(
        256, 0, 98304, 512, 0, imp_b1, 0, imp_w2, nullptr, 256, 0);
    // anomaly + importance + st row0 + final weighted sums -> g_sh/g_sl
    kf<<<BATCH, 256>>>(ad_b2, imp_b2, x, st);
    // ctx[b, z*64+n] = wv_z[n,:] . s[b,z,:] + bv -> g_ch/g_cl [B,256]
    gemm_pl<4, 256, NOSPLIT, 2, 0, 0><<<dim3(128, 1, 4), 256, SMEM_DYN>>>(
        1024, 256, 294912, 256, 16384, b_in + 512, 64, nullptr, nullptr, 256, 64);
    // agg = ctx @ attn_out_w^T + attn_out_b -> d_out tail (fp32)
    gemm_pl<5, 256, NOSPLIT, 0, 0, 0><<<dim3(128, 4, 1), 256, SMEM_DYN>>>(
        256, 0, 360448, 256, 0, b_out, 0, nullptr, agg, 256, 0);
    (void)in_sizes; (void)n_in; (void)out_size;
}